// round 2
// baseline (speedup 1.0000x reference)
#include <cuda_runtime.h>

#define S_LEN  2048
#define HQ     16
#define HKV    2
#define GQA    8
#define DIM    64
#define CSTRIDE 16
#define LC     32
#define LB     64
#define KSEL   8
#define WIN    512
#define SC_N   127     // (2048-32)/16 + 1
#define NOUT   31
#define SCALE  0.125f
#define NTHREADS 256
#define SCS    516     // sc row stride (floats): h*516 mod 32 = h*4 -> conflict-free scatter

__device__ float g_ck[HKV * SC_N * DIM];
__device__ float g_cv[HKV * SC_N * DIM];

// ---------------------------------------------------------------------------
// conv1d compressor
// ---------------------------------------------------------------------------
__global__ void __launch_bounds__(256) compress_kernel(
    const float* __restrict__ k, const float* __restrict__ v,
    const float* __restrict__ wk, const float* __restrict__ wv)
{
    const int b   = blockIdx.x;
    const int hkv = b / SC_N;
    const int c   = b % SC_N;
    __shared__ float ks[LC][DIM];
    __shared__ float vs[LC][DIM];
    __shared__ float red[4][DIM];
    const int tid = threadIdx.x;

    for (int idx = tid; idx < LC * DIM; idx += NTHREADS) {
        int t = idx / DIM, i = idx % DIM;
        int pos = c * CSTRIDE + t;
        ks[t][i] = k[(pos * HKV + hkv) * DIM + i];
        vs[t][i] = v[(pos * HKV + hkv) * DIM + i];
    }
    __syncthreads();

    const int o    = tid & 63;
    const int part = tid >> 6;
    float ak = 0.f, av = 0.f;
    for (int i = part * 16; i < part * 16 + 16; ++i) {
        const float4* wk4 = reinterpret_cast<const float4*>(wk + (o * DIM + i) * LC);
        const float4* wv4 = reinterpret_cast<const float4*>(wv + (o * DIM + i) * LC);
        #pragma unroll
        for (int t4 = 0; t4 < 8; ++t4) {
            float4 a = __ldg(&wk4[t4]);
            float4 bw = __ldg(&wv4[t4]);
            int t = t4 * 4;
            ak += a.x * ks[t][i] + a.y * ks[t + 1][i]
                + a.z * ks[t + 2][i] + a.w * ks[t + 3][i];
            av += bw.x * vs[t][i] + bw.y * vs[t + 1][i]
                + bw.z * vs[t + 2][i] + bw.w * vs[t + 3][i];
        }
    }
    red[part][o] = ak;
    __syncthreads();
    if (part == 0)
        g_ck[(hkv * SC_N + c) * DIM + o] = red[0][o] + red[1][o] + red[2][o] + red[3][o];
    __syncthreads();
    red[part][o] = av;
    __syncthreads();
    if (part == 0)
        g_cv[(hkv * SC_N + c) * DIM + o] = red[0][o] + red[1][o] + red[2][o] + red[3][o];
}

// ---------------------------------------------------------------------------
__device__ __forceinline__ float dot4(float4 a, float4 b) {
    return a.x * b.x + a.y * b.y + a.z * b.z + a.w * b.w;
}

__global__ void __launch_bounds__(256) nsa_mega_kernel(
    const float* __restrict__ q, const float* __restrict__ k,
    const float* __restrict__ v, const float* __restrict__ wg,
    float* __restrict__ out)
{
    const int bx   = blockIdx.x;
    const int s    = bx >> 1;
    const int hkv  = bx & 1;
    const int tid  = threadIdx.x;
    const int lane = tid & 31;
    const int warp = tid >> 5;
    const int h    = lane >> 2;   // 0..7
    const int d16  = lane & 3;    // 0..3, owns d in [d16*16, d16*16+16)

    __shared__ float sc[8 * SCS];
    __shared__ float red[8 * 512];
    __shared__ float o_acc[512];
    __shared__ float pkv[128];
    __shared__ float gsm[24];
    __shared__ int   selblk[8];

    // ---- q fragment in registers: 16 floats of head h, dims [d16*16, +16) ----
    const float4* qrow = reinterpret_cast<const float4*>(q + (s * HQ + hkv * GQA + h) * DIM);
    float4 qf[4];
    #pragma unroll
    for (int r = 0; r < 4; ++r) qf[r] = __ldg(&qrow[d16 * 4 + r]);

    // zero cmp prob region (cols 0..127 must be exact zeros for pooling)
    for (int idx = tid; idx < 8 * 128; idx += NTHREADS)
        sc[(idx >> 7) * SCS + (idx & 127)] = 0.f;

    // ---- gates (warp 0) ----
    if (warp == 0) {
        #pragma unroll
        for (int e = 0; e < 3; ++e) {
            const float4* wrow = reinterpret_cast<const float4*>(wg + e * DIM);
            float a = 0.f;
            #pragma unroll
            for (int r = 0; r < 4; ++r) a += dot4(qf[r], __ldg(&wrow[d16 * 4 + r]));
            a += __shfl_xor_sync(~0u, a, 1);
            a += __shfl_xor_sync(~0u, a, 2);
            if (d16 == 0) gsm[h * 3 + e] = a;
        }
    }

    const int Nc = (s >= 31) ? (((s - 31) >> 4) + 1) : 0;

    // ---- cmp scores: warp per key c ----
    for (int c = warp; c < Nc; c += 8) {
        const float4* kr = reinterpret_cast<const float4*>(g_ck + (hkv * SC_N + c) * DIM);
        float a = 0.f;
        #pragma unroll
        for (int r = 0; r < 4; ++r) a += dot4(qf[r], __ldg(&kr[d16 * 4 + r]));
        a += __shfl_xor_sync(~0u, a, 1);
        a += __shfl_xor_sync(~0u, a, 2);
        if (d16 == 0) sc[h * SCS + c] = a * SCALE;
    }
    __syncthreads();

    // ---- cmp softmax: warp per head ----
    {
        const int hh = warp;
        float vals[4];
        float m = -1e30f;
        #pragma unroll
        for (int r = 0; r < 4; ++r) {
            int c = lane + r * 32;
            vals[r] = (c < Nc) ? sc[hh * SCS + c] : -1e30f;
            m = fmaxf(m, vals[r]);
        }
        #pragma unroll
        for (int off = 16; off; off >>= 1) m = fmaxf(m, __shfl_xor_sync(~0u, m, off));
        float sum = 0.f;
        #pragma unroll
        for (int r = 0; r < 4; ++r) {
            int c = lane + r * 32;
            float p = (c < Nc) ? expf(vals[r] - m) : 0.f;
            vals[r] = p; sum += p;
        }
        #pragma unroll
        for (int off = 16; off; off >>= 1) sum += __shfl_xor_sync(~0u, sum, off);
        float inv = (Nc > 0) ? (1.f / sum) : 0.f;
        #pragma unroll
        for (int r = 0; r < 4; ++r) {
            int c = lane + r * 32;
            sc[hh * SCS + c] = vals[r] * inv;
        }
    }
    __syncthreads();

    if (tid < 127) {
        float a = 0.f;
        #pragma unroll
        for (int hh = 0; hh < 8; ++hh) a += sc[hh * SCS + tid];
        pkv[tid] = a;
    }
    __syncthreads();

    // ---- cmp PV: lane owns (h, 16 d); acc over its c's ----
    float acc[16];
    #pragma unroll
    for (int i = 0; i < 16; ++i) acc[i] = 0.f;
    #pragma unroll 2
    for (int c = warp; c < Nc; c += 8) {
        float p = sc[h * SCS + c];
        const float4* vr = reinterpret_cast<const float4*>(g_cv + (hkv * SC_N + c) * DIM);
        #pragma unroll
        for (int r = 0; r < 4; ++r) {
            float4 t = __ldg(&vr[d16 * 4 + r]);
            acc[r * 4 + 0] += p * t.x; acc[r * 4 + 1] += p * t.y;
            acc[r * 4 + 2] += p * t.z; acc[r * 4 + 3] += p * t.w;
        }
    }
    {
        float4* rd = reinterpret_cast<float4*>(red + warp * 512 + h * 64 + d16 * 16);
        #pragma unroll
        for (int r = 0; r < 4; ++r)
            rd[r] = make_float4(acc[r * 4], acc[r * 4 + 1], acc[r * 4 + 2], acc[r * 4 + 3]);
    }

    // ---- pooling + top-8 (warp 0) ----
    if (warp == 0) {
        float myval;
        if (lane < NOUT) {
            float a = pkv[lane * 4] + pkv[lane * 4 + 1] + pkv[lane * 4 + 2]
                    + pkv[lane * 4 + 3] + pkv[lane * 4 + 4];
            myval = a / 5.0f;
        } else {
            myval = -1.0f;
        }
        if (lane == (s >> 6)) myval = __int_as_float(0x7f800000);
        #pragma unroll
        for (int r = 0; r < KSEL; ++r) {
            float bv = myval; int bi = lane;
            #pragma unroll
            for (int off = 16; off; off >>= 1) {
                float ov = __shfl_xor_sync(~0u, bv, off);
                int   oi = __shfl_xor_sync(~0u, bi, off);
                if (ov > bv || (ov == bv && oi < bi)) { bv = ov; bi = oi; }
            }
            if (lane == 0) selblk[r] = bi;
            if (lane == bi) myval = __int_as_float(0xff800000);
        }
    }
    __syncthreads();

    // reduce cmp PV partials -> o_acc = g2 * cmp
    #pragma unroll
    for (int it = 0; it < 2; ++it) {
        int item = tid + it * NTHREADS;
        int hh = item >> 6;
        float a = 0.f;
        #pragma unroll
        for (int w = 0; w < 8; ++w) a += red[w * 512 + item];
        o_acc[item] = gsm[hh * 3 + 2] * a;
    }
    __syncthreads();

    // ---- branches: 0 = selection, 1 = sliding window ----
    #pragma unroll 1
    for (int br = 0; br < 2; ++br) {
        int nj, lo = 0;
        if (br == 0) {
            nj = KSEL * LB;   // 512
        } else {
            lo = (s >= WIN) ? s - WIN + 1 : 0;
            int n = s - lo + 1;
            nj = ((n + 63) >> 6) << 6;
        }

        // scores: warp per key j
        #pragma unroll 2
        for (int j = warp; j < nj; j += 8) {
            int pos = (br == 0) ? (selblk[j >> 6] * LB + (j & 63)) : (lo + j);
            int pc = min(pos, S_LEN - 1);
            const float4* kr = reinterpret_cast<const float4*>(k + (pc * HKV + hkv) * DIM);
            float a = 0.f;
            #pragma unroll
            for (int r = 0; r < 4; ++r) a += dot4(qf[r], __ldg(&kr[d16 * 4 + r]));
            a += __shfl_xor_sync(~0u, a, 1);
            a += __shfl_xor_sync(~0u, a, 2);
            if (d16 == 0) sc[h * SCS + j] = (pos <= s) ? a * SCALE : -1e30f;
        }
        __syncthreads();

        // softmax: warp per head
        {
            const int hh = warp;
            float m = -1e30f;
            for (int j = lane; j < nj; j += 32) m = fmaxf(m, sc[hh * SCS + j]);
            #pragma unroll
            for (int off = 16; off; off >>= 1) m = fmaxf(m, __shfl_xor_sync(~0u, m, off));
            float sum = 0.f;
            for (int j = lane; j < nj; j += 32) {
                float p = expf(sc[hh * SCS + j] - m);
                sc[hh * SCS + j] = p;
                sum += p;
            }
            #pragma unroll
            for (int off = 16; off; off >>= 1) sum += __shfl_xor_sync(~0u, sum, off);
            float inv = 1.f / sum;
            for (int j = lane; j < nj; j += 32) sc[hh * SCS + j] *= inv;
        }
        __syncthreads();

        // PV: lane owns (h, 16 d)
        #pragma unroll
        for (int i = 0; i < 16; ++i) acc[i] = 0.f;
        #pragma unroll 2
        for (int j = warp; j < nj; j += 8) {
            int pos = (br == 0) ? (selblk[j >> 6] * LB + (j & 63)) : (lo + j);
            int pc = min(pos, S_LEN - 1);
            float p = sc[h * SCS + j];
            const float4* vr = reinterpret_cast<const float4*>(v + (pc * HKV + hkv) * DIM);
            #pragma unroll
            for (int r = 0; r < 4; ++r) {
                float4 t = __ldg(&vr[d16 * 4 + r]);
                acc[r * 4 + 0] += p * t.x; acc[r * 4 + 1] += p * t.y;
                acc[r * 4 + 2] += p * t.z; acc[r * 4 + 3] += p * t.w;
            }
        }
        {
            float4* rd = reinterpret_cast<float4*>(red + warp * 512 + h * 64 + d16 * 16);
            #pragma unroll
            for (int r = 0; r < 4; ++r)
                rd[r] = make_float4(acc[r * 4], acc[r * 4 + 1], acc[r * 4 + 2], acc[r * 4 + 3]);
        }
        __syncthreads();
        #pragma unroll
        for (int it = 0; it < 2; ++it) {
            int item = tid + it * NTHREADS;
            int hh = item >> 6;
            float a = 0.f;
            #pragma unroll
            for (int w = 0; w < 8; ++w) a += red[w * 512 + item];
            o_acc[item] += gsm[hh * 3 + br] * a;
        }
        __syncthreads();
    }

    // ---- store ----
    #pragma unroll
    for (int it = 0; it < 2; ++it) {
        int item = tid + it * NTHREADS;
        int hh = item >> 6, d = item & 63;
        out[(s * HQ + hkv * GQA + hh) * DIM + d] = o_acc[item];
    }
}

// ---------------------------------------------------------------------------
extern "C" void kernel_launch(void* const* d_in, const int* in_sizes, int n_in,
                              void* d_out, int out_size)
{
    const float* q  = (const float*)d_in[0];
    const float* k  = (const float*)d_in[1];
    const float* v  = (const float*)d_in[2];
    const float* wk = (const float*)d_in[3];
    const float* wv = (const float*)d_in[4];
    const float* wg = (const float*)d_in[5];
    float* out = (float*)d_out;

    compress_kernel<<<HKV * SC_N, NTHREADS>>>(k, v, wk, wv);
    nsa_mega_kernel<<<S_LEN * HKV, NTHREADS>>>(q, k, v, wg, out);
}

// round 3
// speedup vs baseline: 1.0610x; 1.0610x over previous
#include <cuda_runtime.h>

#define S_LEN  2048
#define HKV    2
#define HQ     16
#define GQA    8
#define DIM    64
#define LC     32
#define CSTRIDE 16
#define LB     64
#define KSEL   8
#define WIN    512
#define SC_N   127
#define NOUT   31
#define SCALE  0.125f
#define QT     8
#define NT     256

__device__ float g_ck[HKV * SC_N * DIM];
__device__ float g_cv[HKV * SC_N * DIM];

__device__ __forceinline__ float dot4(float4 a, float4 b) {
    return a.x * b.x + a.y * b.y + a.z * b.z + a.w * b.w;
}

// ---------------------------------------------------------------------------
// conv1d compressor: block = (hkv, group of 4 compressed positions)
// ---------------------------------------------------------------------------
__global__ void __launch_bounds__(256) compress_kernel(
    const float* __restrict__ k, const float* __restrict__ v,
    const float* __restrict__ wk, const float* __restrict__ wv)
{
    const int hkv = blockIdx.x & 1;
    const int cg  = blockIdx.x >> 1;     // 0..31
    const int c0  = cg * 4;
    __shared__ float ks[80 * 64];
    __shared__ float vs[80 * 64];
    __shared__ float red[4 * 4 * 64];
    const int tid = threadIdx.x;

    for (int idx = tid; idx < 80 * 16; idx += NT) {
        int row = idx >> 4, quad = idx & 15;
        int pos = c0 * CSTRIDE + row;
        float4 kk = make_float4(0.f, 0.f, 0.f, 0.f);
        float4 vv = kk;
        if (pos < S_LEN) {
            kk = __ldg((const float4*)(k + (pos * HKV + hkv) * DIM) + quad);
            vv = __ldg((const float4*)(v + (pos * HKV + hkv) * DIM) + quad);
        }
        ((float4*)(ks + row * 64))[quad] = kk;
        ((float4*)(vs + row * 64))[quad] = vv;
    }
    __syncthreads();

    const int o    = tid & 63;
    const int part = tid >> 6;
    float ak[4] = {0.f, 0.f, 0.f, 0.f};
    float av[4] = {0.f, 0.f, 0.f, 0.f};
    for (int i = part * 16; i < part * 16 + 16; ++i) {
        const float4* wk4 = (const float4*)(wk + (o * DIM + i) * LC);
        const float4* wv4 = (const float4*)(wv + (o * DIM + i) * LC);
        #pragma unroll
        for (int t4 = 0; t4 < 8; ++t4) {
            float4 a  = __ldg(&wk4[t4]);
            float4 bw = __ldg(&wv4[t4]);
            int t = t4 * 4;
            #pragma unroll
            for (int cc = 0; cc < 4; ++cc) {
                const float* kr = ks + (cc * 16 + t) * 64 + i;
                const float* vr = vs + (cc * 16 + t) * 64 + i;
                ak[cc] += a.x  * kr[0] + a.y  * kr[64] + a.z  * kr[128] + a.w  * kr[192];
                av[cc] += bw.x * vr[0] + bw.y * vr[64] + bw.z * vr[128] + bw.w * vr[192];
            }
        }
    }
    #pragma unroll
    for (int cc = 0; cc < 4; ++cc) red[(part * 4 + cc) * 64 + o] = ak[cc];
    __syncthreads();
    if (part == 0) {
        #pragma unroll
        for (int cc = 0; cc < 4; ++cc) {
            if (c0 + cc < SC_N)
                g_ck[(hkv * SC_N + c0 + cc) * DIM + o] =
                    red[cc * 64 + o] + red[(4 + cc) * 64 + o]
                  + red[(8 + cc) * 64 + o] + red[(12 + cc) * 64 + o];
        }
    }
    __syncthreads();
    #pragma unroll
    for (int cc = 0; cc < 4; ++cc) red[(part * 4 + cc) * 64 + o] = av[cc];
    __syncthreads();
    if (part == 0) {
        #pragma unroll
        for (int cc = 0; cc < 4; ++cc) {
            if (c0 + cc < SC_N)
                g_cv[(hkv * SC_N + c0 + cc) * DIM + o] =
                    red[cc * 64 + o] + red[(4 + cc) * 64 + o]
                  + red[(8 + cc) * 64 + o] + red[(12 + cc) * 64 + o];
        }
    }
}

// ---------------------------------------------------------------------------
// Mega kernel: CTA = (hkv, 8 queries). warp = query. lane = (h = lane>>2, d16 = lane&3)
// ---------------------------------------------------------------------------
__global__ void __launch_bounds__(256, 2) nsa_kernel(
    const float* __restrict__ q, const float* __restrict__ k,
    const float* __restrict__ v, const float* __restrict__ wg,
    float* __restrict__ out)
{
    extern __shared__ float pool[];      // 13056 floats
    __shared__ unsigned selmaskArr[QT];
    __shared__ unsigned cmbShared;

    const int bx   = blockIdx.x;
    const int hkv  = bx & 1;
    const int s0   = (bx >> 1) * QT;
    const int tid  = threadIdx.x;
    const int lane = tid & 31;
    const int warp = tid >> 5;
    const int s    = s0 + warp;
    const int h    = lane >> 2;
    const int d16  = lane & 3;

    // region map (phase 1): scq [QT][8][132] @0 (8448), pkv [QT][128] @8448
    // region map (phase 2): Kt [64][68] @0, Vt @4352, scT [QT][8][68] @8704
    float* scq  = pool;
    float* pkvA = pool + QT * 8 * 132;
    float* Kt   = pool;
    float* Vt   = pool + 4352;
    float* scT  = pool + 8704;

    // ---- q fragment (own head h, dims d16*16..+16) ----
    const float4* qrow = (const float4*)(q + (s * HQ + hkv * GQA + h) * DIM);
    float4 qf[4];
    #pragma unroll
    for (int r = 0; r < 4; ++r) qf[r] = __ldg(&qrow[d16 * 4 + r]);

    // ---- gates ----
    float gate[3];
    #pragma unroll
    for (int e = 0; e < 3; ++e) {
        const float4* wrow = (const float4*)(wg + e * DIM);
        float a = 0.f;
        #pragma unroll
        for (int r = 0; r < 4; ++r) a += dot4(qf[r], __ldg(&wrow[d16 * 4 + r]));
        a += __shfl_xor_sync(~0u, a, 1);
        a += __shfl_xor_sync(~0u, a, 2);
        gate[e] = a;
    }

    const int Nc = (s >= 31) ? (((s - 31) >> 4) + 1) : 0;
    const float* ckb = g_ck + hkv * SC_N * DIM;
    const float* cvb = g_cv + hkv * SC_N * DIM;

    // ---- cmp scores (warp = query; one key per iteration; all lanes get score) ----
    for (int c = 0; c < Nc; ++c) {
        const float4* kr = (const float4*)(ckb + c * DIM);
        float a = 0.f;
        #pragma unroll
        for (int r = 0; r < 4; ++r) a += dot4(qf[r], __ldg(&kr[d16 * 4 + r]));
        a += __shfl_xor_sync(~0u, a, 1);
        a += __shfl_xor_sync(~0u, a, 2);
        if (d16 == 0) scq[(warp * 8 + h) * 132 + c] = a * SCALE;
    }
    __syncwarp();

    // ---- cmp softmax per head (exact expf; probs feed selection) ----
    for (int hh = 0; hh < 8; ++hh) {
        float* row = scq + (warp * 8 + hh) * 132;
        float m = -1e30f;
        for (int c = lane; c < Nc; c += 32) m = fmaxf(m, row[c]);
        #pragma unroll
        for (int off = 16; off; off >>= 1) m = fmaxf(m, __shfl_xor_sync(~0u, m, off));
        float sum = 0.f;
        for (int c = lane; c < Nc; c += 32) {
            float p = expf(row[c] - m);
            row[c] = p; sum += p;
        }
        #pragma unroll
        for (int off = 16; off; off >>= 1) sum += __shfl_xor_sync(~0u, sum, off);
        float inv = (sum > 0.f) ? (1.f / sum) : 0.f;
        for (int c = lane; c < 128; c += 32)
            row[c] = (c < Nc) ? row[c] * inv : 0.f;
    }
    __syncwarp();

    // ---- p_kv (sum over heads) ----
    for (int c = lane; c < 128; c += 32) {
        float a = 0.f;
        #pragma unroll
        for (int hh = 0; hh < 8; ++hh) a += scq[(warp * 8 + hh) * 132 + c];
        pkvA[warp * 128 + c] = a;
    }
    __syncwarp();

    // ---- pooling + top-8 -> selection bitmask ----
    {
        float myval;
        if (lane < NOUT) {
            const float* pv = pkvA + warp * 128 + lane * 4;
            myval = (pv[0] + pv[1] + pv[2] + pv[3] + pv[4]) / 5.0f;
        } else {
            myval = -1.0f;
        }
        if (lane == (s >> 6)) myval = __int_as_float(0x7f800000);
        unsigned mask = 0;
        #pragma unroll
        for (int r = 0; r < KSEL; ++r) {
            float bv = myval; int bi = lane;
            #pragma unroll
            for (int off = 16; off; off >>= 1) {
                float ov = __shfl_xor_sync(~0u, bv, off);
                int   oi = __shfl_xor_sync(~0u, bi, off);
                if (ov > bv || (ov == bv && oi < bi)) { bv = ov; bi = oi; }
            }
            mask |= 1u << bi;
            if (lane == bi) myval = __int_as_float(0xff800000);
        }
        if (lane == 0) selmaskArr[warp] = mask;
    }
    __syncwarp();

    // ---- cmp PV folded into output accumulator with gate2 ----
    float outAcc[16];
    #pragma unroll
    for (int i = 0; i < 16; ++i) outAcc[i] = 0.f;
    const float g2 = gate[2];
    for (int c = 0; c < Nc; ++c) {
        float p = scq[(warp * 8 + h) * 132 + c] * g2;
        const float4* vr = (const float4*)(cvb + c * DIM);
        #pragma unroll
        for (int r = 0; r < 4; ++r) {
            float4 t = __ldg(&vr[d16 * 4 + r]);
            outAcc[r * 4 + 0] += p * t.x; outAcc[r * 4 + 1] += p * t.y;
            outAcc[r * 4 + 2] += p * t.z; outAcc[r * 4 + 3] += p * t.w;
        }
    }

    __syncthreads();   // all warps done with scq/pkv; selmasks ready
    if (tid == 0) {
        unsigned cmb = 0;
        #pragma unroll
        for (int qq = 0; qq < QT; ++qq) cmb |= selmaskArr[qq];
        int loS = s0 - (WIN - 1); if (loS < 0) loS = 0;
        int lowBlk = loS >> 6;
        int hiBlk  = (s0 + QT - 1) >> 6;
        unsigned wmask = (hiBlk >= 31 ? 0xFFFFFFFFu : ((1u << (hiBlk + 1)) - 1u))
                       & ~((1u << lowBlk) - 1u);
        cmbShared = cmb | wmask;
    }
    __syncthreads();

    const unsigned selMine = selmaskArr[warp];
    unsigned rem = cmbShared;

    float accS[16], accW[16];
    #pragma unroll
    for (int i = 0; i < 16; ++i) { accS[i] = 0.f; accW[i] = 0.f; }
    float mS = -1e30f, lS = 0.f, mW = -1e30f, lW = 0.f;

    float* myScRow = scT + warp * 544 + h * 68;

    while (rem) {
        int b = __ffs(rem) - 1;
        rem &= rem - 1;
        const int base = b * LB;

        __syncthreads();   // previous tile fully consumed
        for (int idx = tid; idx < 1024; idx += NT) {
            int row = idx >> 4, quad = idx & 15;
            int pos = base + row;
            ((float4*)(Kt + row * 68))[quad] =
                __ldg((const float4*)(k + (pos * HKV + hkv) * DIM) + quad);
            ((float4*)(Vt + row * 68))[quad] =
                __ldg((const float4*)(v + (pos * HKV + hkv) * DIM) + quad);
        }
        __syncthreads();

        const bool selAct = (selMine >> b) & 1u;
        const bool swaAct = (base <= s) && (base + 63 >= s - (WIN - 1));
        if (selAct || swaAct) {
            // phase A: raw scores for this tile
            #pragma unroll 2
            for (int j = 0; j < 64; ++j) {
                const float4* krj = (const float4*)(Kt + j * 68) + d16 * 4;
                float a = dot4(qf[0], krj[0]) + dot4(qf[1], krj[1])
                        + dot4(qf[2], krj[2]) + dot4(qf[3], krj[3]);
                a += __shfl_xor_sync(~0u, a, 1);
                a += __shfl_xor_sync(~0u, a, 2);
                if (d16 == 0) myScRow[j] = a * SCALE;
            }
            __syncwarp();

            // tile maxima under branch masks
            float tS = -1e30f, tW = -1e30f;
            {
                int j0 = d16 * 16;
                #pragma unroll
                for (int jj = 0; jj < 16; ++jj) {
                    int j = j0 + jj;
                    int pos = base + j;
                    float sc = myScRow[j];
                    if (pos <= s) {
                        tS = fmaxf(tS, sc);
                        if (pos >= s - (WIN - 1)) tW = fmaxf(tW, sc);
                    }
                }
                tS = fmaxf(tS, __shfl_xor_sync(~0u, tS, 1));
                tS = fmaxf(tS, __shfl_xor_sync(~0u, tS, 2));
                tW = fmaxf(tW, __shfl_xor_sync(~0u, tW, 1));
                tW = fmaxf(tW, __shfl_xor_sync(~0u, tW, 2));
            }
            const bool doS = selAct && (tS > -1e29f);
            const bool doW = swaAct && (tW > -1e29f);
            if (doS) {
                float mN = fmaxf(mS, tS);
                float sc2 = __expf(mS - mN);
                lS *= sc2;
                #pragma unroll
                for (int i = 0; i < 16; ++i) accS[i] *= sc2;
                mS = mN;
            }
            if (doW) {
                float mN = fmaxf(mW, tW);
                float sc2 = __expf(mW - mN);
                lW *= sc2;
                #pragma unroll
                for (int i = 0; i < 16; ++i) accW[i] *= sc2;
                mW = mN;
            }
            if (doS || doW) {
                #pragma unroll 2
                for (int j = 0; j < 64; ++j) {
                    int pos = base + j;
                    float sc = myScRow[j];
                    const float4* vrj = (const float4*)(Vt + j * 68) + d16 * 4;
                    float4 v0 = vrj[0], v1 = vrj[1], v2 = vrj[2], v3 = vrj[3];
                    if (doS) {
                        float p = (pos <= s) ? __expf(sc - mS) : 0.f;
                        lS += p;
                        accS[0]  += p * v0.x; accS[1]  += p * v0.y;
                        accS[2]  += p * v0.z; accS[3]  += p * v0.w;
                        accS[4]  += p * v1.x; accS[5]  += p * v1.y;
                        accS[6]  += p * v1.z; accS[7]  += p * v1.w;
                        accS[8]  += p * v2.x; accS[9]  += p * v2.y;
                        accS[10] += p * v2.z; accS[11] += p * v2.w;
                        accS[12] += p * v3.x; accS[13] += p * v3.y;
                        accS[14] += p * v3.z; accS[15] += p * v3.w;
                    }
                    if (doW) {
                        float p = (pos <= s && pos >= s - (WIN - 1)) ? __expf(sc - mW) : 0.f;
                        lW += p;
                        accW[0]  += p * v0.x; accW[1]  += p * v0.y;
                        accW[2]  += p * v0.z; accW[3]  += p * v0.w;
                        accW[4]  += p * v1.x; accW[5]  += p * v1.y;
                        accW[6]  += p * v1.z; accW[7]  += p * v1.w;
                        accW[8]  += p * v2.x; accW[9]  += p * v2.y;
                        accW[10] += p * v2.z; accW[11] += p * v2.w;
                        accW[12] += p * v3.x; accW[13] += p * v3.y;
                        accW[14] += p * v3.z; accW[15] += p * v3.w;
                    }
                }
            }
        }
    }

    // ---- combine and store ----
    const float invS = gate[0] / fmaxf(lS, 1e-20f);
    const float invW = gate[1] / fmaxf(lW, 1e-20f);
    float4* orow = (float4*)(out + (s * HQ + hkv * GQA + h) * DIM);
    #pragma unroll
    for (int r = 0; r < 4; ++r) {
        float4 o;
        o.x = outAcc[r * 4 + 0] + invS * accS[r * 4 + 0] + invW * accW[r * 4 + 0];
        o.y = outAcc[r * 4 + 1] + invS * accS[r * 4 + 1] + invW * accW[r * 4 + 1];
        o.z = outAcc[r * 4 + 2] + invS * accS[r * 4 + 2] + invW * accW[r * 4 + 2];
        o.w = outAcc[r * 4 + 3] + invS * accS[r * 4 + 3] + invW * accW[r * 4 + 3];
        orow[d16 * 4 + r] = o;
    }
}

// ---------------------------------------------------------------------------
extern "C" void kernel_launch(void* const* d_in, const int* in_sizes, int n_in,
                              void* d_out, int out_size)
{
    const float* q  = (const float*)d_in[0];
    const float* k  = (const float*)d_in[1];
    const float* v  = (const float*)d_in[2];
    const float* wk = (const float*)d_in[3];
    const float* wv = (const float*)d_in[4];
    const float* wg = (const float*)d_in[5];
    float* out = (float*)d_out;

    compress_kernel<<<64, NT>>>(k, v, wk, wv);

    const size_t smem_bytes = 13056 * sizeof(float);
    cudaFuncSetAttribute(nsa_kernel,
                         cudaFuncAttributeMaxDynamicSharedMemorySize, (int)smem_bytes);
    nsa_kernel<<<(S_LEN / QT) * HKV, NT, smem_bytes>>>(q, k, v, wg, out);
}

// round 4
// speedup vs baseline: 1.0859x; 1.0235x over previous
#include <cuda_runtime.h>

#define S_LEN  2048
#define HKV    2
#define HQ     16
#define GQA    8
#define DIM    64
#define LC     32
#define CSTRIDE 16
#define LB     64
#define KSEL   8
#define WIN    512
#define SC_N   127
#define NOUT   31
#define SCALE  0.125f
#define QT     8
#define NT     256

__device__ float g_ck[HKV * SC_N * DIM];
__device__ float g_cv[HKV * SC_N * DIM];
__device__ unsigned g_selmask[HKV * S_LEN];

__device__ __forceinline__ float dot4(float4 a, float4 b) {
    return a.x * b.x + a.y * b.y + a.z * b.z + a.w * b.w;
}

// ---------------------------------------------------------------------------
// conv1d compressor: block = (hkv, group of 4 compressed positions)
// ---------------------------------------------------------------------------
__global__ void __launch_bounds__(256) compress_kernel(
    const float* __restrict__ k, const float* __restrict__ v,
    const float* __restrict__ wk, const float* __restrict__ wv)
{
    const int hkv = blockIdx.x & 1;
    const int c0  = (blockIdx.x >> 1) * 4;
    __shared__ float ks[80 * 64];
    __shared__ float vs[80 * 64];
    __shared__ float red[16 * 64];
    const int tid = threadIdx.x;

    for (int idx = tid; idx < 80 * 16; idx += NT) {
        int row = idx >> 4, quad = idx & 15;
        int pos = c0 * CSTRIDE + row;
        float4 kk = make_float4(0.f, 0.f, 0.f, 0.f);
        float4 vv = kk;
        if (pos < S_LEN) {
            kk = __ldg((const float4*)(k + (pos * HKV + hkv) * DIM) + quad);
            vv = __ldg((const float4*)(v + (pos * HKV + hkv) * DIM) + quad);
        }
        ((float4*)(ks + row * 64))[quad] = kk;
        ((float4*)(vs + row * 64))[quad] = vv;
    }
    __syncthreads();

    const int o    = tid & 63;
    const int part = tid >> 6;
    float ak[4] = {0.f, 0.f, 0.f, 0.f};
    float av[4] = {0.f, 0.f, 0.f, 0.f};
    for (int i = part * 16; i < part * 16 + 16; ++i) {
        const float4* wk4 = (const float4*)(wk + (o * DIM + i) * LC);
        const float4* wv4 = (const float4*)(wv + (o * DIM + i) * LC);
        #pragma unroll
        for (int t4 = 0; t4 < 8; ++t4) {
            float4 a  = __ldg(&wk4[t4]);
            float4 bw = __ldg(&wv4[t4]);
            int t = t4 * 4;
            #pragma unroll
            for (int cc = 0; cc < 4; ++cc) {
                const float* kr = ks + (cc * 16 + t) * 64 + i;
                const float* vr = vs + (cc * 16 + t) * 64 + i;
                ak[cc] += a.x  * kr[0] + a.y  * kr[64] + a.z  * kr[128] + a.w  * kr[192];
                av[cc] += bw.x * vr[0] + bw.y * vr[64] + bw.z * vr[128] + bw.w * vr[192];
            }
        }
    }
    #pragma unroll
    for (int cc = 0; cc < 4; ++cc) red[(part * 4 + cc) * 64 + o] = ak[cc];
    __syncthreads();
    if (part == 0) {
        #pragma unroll
        for (int cc = 0; cc < 4; ++cc)
            if (c0 + cc < SC_N)
                g_ck[(hkv * SC_N + c0 + cc) * DIM + o] =
                    red[cc * 64 + o] + red[(4 + cc) * 64 + o]
                  + red[(8 + cc) * 64 + o] + red[(12 + cc) * 64 + o];
    }
    __syncthreads();
    #pragma unroll
    for (int cc = 0; cc < 4; ++cc) red[(part * 4 + cc) * 64 + o] = av[cc];
    __syncthreads();
    if (part == 0) {
        #pragma unroll
        for (int cc = 0; cc < 4; ++cc)
            if (c0 + cc < SC_N)
                g_cv[(hkv * SC_N + c0 + cc) * DIM + o] =
                    red[cc * 64 + o] + red[(4 + cc) * 64 + o]
                  + red[(8 + cc) * 64 + o] + red[(12 + cc) * 64 + o];
    }
}

// ---------------------------------------------------------------------------
// Kernel 2: compressed attention + block selection.
// CTA = (hkv, 8 queries), warp = query, lane = (h = lane>>2, d16 = lane&3).
// Writes gate2*cmp_o to out, selection bitmask to g_selmask.
// ---------------------------------------------------------------------------
__global__ void __launch_bounds__(256) cmp_kernel(
    const float* __restrict__ q, const float* __restrict__ wg,
    float* __restrict__ out)
{
    __shared__ float scq[QT * 8 * 132];
    __shared__ float pkvA[QT * 128];

    const int bx   = blockIdx.x;
    const int hkv  = bx & 1;
    const int s0   = (bx >> 1) * QT;
    const int tid  = threadIdx.x;
    const int lane = tid & 31;
    const int warp = tid >> 5;
    const int s    = s0 + warp;
    const int h    = lane >> 2;
    const int d16  = lane & 3;

    const float4* qrow = (const float4*)(q + (s * HQ + hkv * GQA + h) * DIM);
    float4 qf[4];
    #pragma unroll
    for (int r = 0; r < 4; ++r) qf[r] = __ldg(&qrow[d16 * 4 + r]);

    // gate2
    float g2;
    {
        const float4* wrow = (const float4*)(wg + 2 * DIM);
        float a = 0.f;
        #pragma unroll
        for (int r = 0; r < 4; ++r) a += dot4(qf[r], __ldg(&wrow[d16 * 4 + r]));
        a += __shfl_xor_sync(~0u, a, 1);
        a += __shfl_xor_sync(~0u, a, 2);
        g2 = a;
    }

    const int Nc = (s >= 31) ? (((s - 31) >> 4) + 1) : 0;
    const float* ckb = g_ck + hkv * SC_N * DIM;
    const float* cvb = g_cv + hkv * SC_N * DIM;

    for (int c = 0; c < Nc; ++c) {
        const float4* kr = (const float4*)(ckb + c * DIM);
        float a = 0.f;
        #pragma unroll
        for (int r = 0; r < 4; ++r) a += dot4(qf[r], __ldg(&kr[d16 * 4 + r]));
        a += __shfl_xor_sync(~0u, a, 1);
        a += __shfl_xor_sync(~0u, a, 2);
        if (d16 == 0) scq[(warp * 8 + h) * 132 + c] = a * SCALE;
    }
    __syncwarp();

    // exact softmax per head (probs feed top-k selection)
    for (int hh = 0; hh < 8; ++hh) {
        float* row = scq + (warp * 8 + hh) * 132;
        float m = -1e30f;
        for (int c = lane; c < Nc; c += 32) m = fmaxf(m, row[c]);
        #pragma unroll
        for (int off = 16; off; off >>= 1) m = fmaxf(m, __shfl_xor_sync(~0u, m, off));
        float sum = 0.f;
        for (int c = lane; c < Nc; c += 32) {
            float p = expf(row[c] - m);
            row[c] = p; sum += p;
        }
        #pragma unroll
        for (int off = 16; off; off >>= 1) sum += __shfl_xor_sync(~0u, sum, off);
        float inv = (sum > 0.f) ? (1.f / sum) : 0.f;
        for (int c = lane; c < 128; c += 32)
            row[c] = (c < Nc) ? row[c] * inv : 0.f;
    }
    __syncwarp();

    for (int c = lane; c < 128; c += 32) {
        float a = 0.f;
        #pragma unroll
        for (int hh = 0; hh < 8; ++hh) a += scq[(warp * 8 + hh) * 132 + c];
        pkvA[warp * 128 + c] = a;
    }
    __syncwarp();

    // pooling + top-8 (lax.top_k tie-break: value desc, index asc)
    {
        float myval;
        if (lane < NOUT) {
            const float* pv = pkvA + warp * 128 + lane * 4;
            myval = (pv[0] + pv[1] + pv[2] + pv[3] + pv[4]) / 5.0f;
        } else {
            myval = -1.0f;
        }
        if (lane == (s >> 6)) myval = __int_as_float(0x7f800000);
        unsigned mask = 0;
        #pragma unroll
        for (int r = 0; r < KSEL; ++r) {
            float bv = myval; int bi = lane;
            #pragma unroll
            for (int off = 16; off; off >>= 1) {
                float ov = __shfl_xor_sync(~0u, bv, off);
                int   oi = __shfl_xor_sync(~0u, bi, off);
                if (ov > bv || (ov == bv && oi < bi)) { bv = ov; bi = oi; }
            }
            mask |= 1u << bi;
            if (lane == bi) myval = __int_as_float(0xff800000);
        }
        if (lane == 0) g_selmask[hkv * S_LEN + s] = mask;
    }

    // cmp PV -> out = g2 * cmp
    float acc[16];
    #pragma unroll
    for (int i = 0; i < 16; ++i) acc[i] = 0.f;
    for (int c = 0; c < Nc; ++c) {
        float p = scq[(warp * 8 + h) * 132 + c];
        const float4* vr = (const float4*)(cvb + c * DIM);
        #pragma unroll
        for (int r = 0; r < 4; ++r) {
            float4 t = __ldg(&vr[d16 * 4 + r]);
            acc[r * 4 + 0] += p * t.x; acc[r * 4 + 1] += p * t.y;
            acc[r * 4 + 2] += p * t.z; acc[r * 4 + 3] += p * t.w;
        }
    }
    float4* orow = (float4*)(out + (s * HQ + hkv * GQA + h) * DIM);
    #pragma unroll
    for (int r = 0; r < 4; ++r)
        orow[d16 * 4 + r] = make_float4(g2 * acc[r * 4],     g2 * acc[r * 4 + 1],
                                        g2 * acc[r * 4 + 2], g2 * acc[r * 4 + 3]);
}

// ---------------------------------------------------------------------------
// Kernel 3: selection + sliding-window branches (union tiles, single-exp).
// ---------------------------------------------------------------------------
extern __shared__ float pool3[];

__global__ void __launch_bounds__(256, 3) branch_kernel(
    const float* __restrict__ q, const float* __restrict__ k,
    const float* __restrict__ v, const float* __restrict__ wg,
    float* __restrict__ out)
{
    __shared__ unsigned selmaskSh[QT];
    __shared__ unsigned cmbShared;

    float* Kt  = pool3;           // [64][68]
    float* Vt  = pool3 + 4352;    // [64][68]
    float* scT = pool3 + 8704;    // [QT][8][68]

    const int bx   = blockIdx.x;
    const int hkv  = bx & 1;
    const int s0   = (bx >> 1) * QT;
    const int tid  = threadIdx.x;
    const int lane = tid & 31;
    const int warp = tid >> 5;
    const int s    = s0 + warp;
    const int h    = lane >> 2;
    const int d16  = lane & 3;

    const float4* qrow = (const float4*)(q + (s * HQ + hkv * GQA + h) * DIM);
    float4 qf[4];
    #pragma unroll
    for (int r = 0; r < 4; ++r) qf[r] = __ldg(&qrow[d16 * 4 + r]);

    float gate0, gate1;
    #pragma unroll
    for (int e = 0; e < 2; ++e) {
        const float4* wrow = (const float4*)(wg + e * DIM);
        float a = 0.f;
        #pragma unroll
        for (int r = 0; r < 4; ++r) a += dot4(qf[r], __ldg(&wrow[d16 * 4 + r]));
        a += __shfl_xor_sync(~0u, a, 1);
        a += __shfl_xor_sync(~0u, a, 2);
        if (e == 0) gate0 = a; else gate1 = a;
    }

    if (lane == 0) selmaskSh[warp] = g_selmask[hkv * S_LEN + s];
    __syncthreads();
    if (tid == 0) {
        unsigned cmb = 0;
        #pragma unroll
        for (int qq = 0; qq < QT; ++qq) cmb |= selmaskSh[qq];
        int loS = s0 - (WIN - 1); if (loS < 0) loS = 0;
        int lowBlk = loS >> 6;
        int hiBlk  = (s0 + QT - 1) >> 6;
        unsigned wmask = (hiBlk >= 31 ? 0xFFFFFFFFu : ((1u << (hiBlk + 1)) - 1u))
                       & ~((1u << lowBlk) - 1u);
        cmbShared = cmb | wmask;
    }
    __syncthreads();

    const unsigned selMine = selmaskSh[warp];
    unsigned rem = cmbShared;

    float accS[16], accW[16];
    #pragma unroll
    for (int i = 0; i < 16; ++i) { accS[i] = 0.f; accW[i] = 0.f; }
    float mU = -1e30f, lS = 0.f, lW = 0.f;
    float* myScRow = scT + warp * 544 + h * 68;
    const int winLo = s - (WIN - 1);

    while (rem) {
        int b = __ffs(rem) - 1;
        rem &= rem - 1;
        const int base = b * LB;

        __syncthreads();
        for (int idx = tid; idx < 1024; idx += NT) {
            int row = idx >> 4, quad = idx & 15;
            int pos = base + row;
            ((float4*)(Kt + row * 68))[quad] =
                __ldg((const float4*)(k + (pos * HKV + hkv) * DIM) + quad);
            ((float4*)(Vt + row * 68))[quad] =
                __ldg((const float4*)(v + (pos * HKV + hkv) * DIM) + quad);
        }
        __syncthreads();

        if (base > s) continue;                       // warp-local skip
        const bool selAct = (selMine >> b) & 1u;
        const bool swaAct = (base + 63) >= winLo;     // base<=s already true
        if (!(selAct || swaAct)) continue;

        // ---- scores + running masked maxima ----
        float tS = -1e30f, tW = -1e30f;
        const int jhi = min(63, s - base);
        #pragma unroll 2
        for (int j = 0; j < 64; ++j) {
            const float4* krj = (const float4*)(Kt + j * 68) + d16 * 4;
            float a = dot4(qf[0], krj[0]) + dot4(qf[1], krj[1])
                    + dot4(qf[2], krj[2]) + dot4(qf[3], krj[3]);
            a += __shfl_xor_sync(~0u, a, 1);
            a += __shfl_xor_sync(~0u, a, 2);
            float sc = a * SCALE;
            if (d16 == 0) myScRow[j] = sc;
            if (j <= jhi) {
                tS = fmaxf(tS, sc);
                if (base + j >= winLo) tW = fmaxf(tW, sc);
            }
        }
        __syncwarp();

        const bool doS = selAct;                      // jhi>=0 guaranteed (base<=s)
        const bool doW = swaAct && (tW > -1e29f);
        float t = -1e30f;
        if (doS) t = tS;
        if (doW) t = fmaxf(t, tW);
        if (t > mU) {
            float f = __expf(mU - t);
            lS *= f; lW *= f;
            #pragma unroll
            for (int i = 0; i < 16; ++i) { accS[i] *= f; accW[i] *= f; }
            mU = t;
        }

        const int jlo = max(0, winLo - base);
        if (doS && doW) {
            for (int j = 0; j <= jhi; ++j) {
                float e = __expf(myScRow[j] - mU);
                const float4* vrj = (const float4*)(Vt + j * 68) + d16 * 4;
                float4 v0 = vrj[0], v1 = vrj[1], v2 = vrj[2], v3 = vrj[3];
                lS += e;
                accS[0]  += e * v0.x; accS[1]  += e * v0.y;
                accS[2]  += e * v0.z; accS[3]  += e * v0.w;
                accS[4]  += e * v1.x; accS[5]  += e * v1.y;
                accS[6]  += e * v1.z; accS[7]  += e * v1.w;
                accS[8]  += e * v2.x; accS[9]  += e * v2.y;
                accS[10] += e * v2.z; accS[11] += e * v2.w;
                accS[12] += e * v3.x; accS[13] += e * v3.y;
                accS[14] += e * v3.z; accS[15] += e * v3.w;
                if (j >= jlo) {
                    lW += e;
                    accW[0]  += e * v0.x; accW[1]  += e * v0.y;
                    accW[2]  += e * v0.z; accW[3]  += e * v0.w;
                    accW[4]  += e * v1.x; accW[5]  += e * v1.y;
                    accW[6]  += e * v1.z; accW[7]  += e * v1.w;
                    accW[8]  += e * v2.x; accW[9]  += e * v2.y;
                    accW[10] += e * v2.z; accW[11] += e * v2.w;
                    accW[12] += e * v3.x; accW[13] += e * v3.y;
                    accW[14] += e * v3.z; accW[15] += e * v3.w;
                }
            }
        } else if (doS) {
            for (int j = 0; j <= jhi; ++j) {
                float e = __expf(myScRow[j] - mU);
                const float4* vrj = (const float4*)(Vt + j * 68) + d16 * 4;
                float4 v0 = vrj[0], v1 = vrj[1], v2 = vrj[2], v3 = vrj[3];
                lS += e;
                accS[0]  += e * v0.x; accS[1]  += e * v0.y;
                accS[2]  += e * v0.z; accS[3]  += e * v0.w;
                accS[4]  += e * v1.x; accS[5]  += e * v1.y;
                accS[6]  += e * v1.z; accS[7]  += e * v1.w;
                accS[8]  += e * v2.x; accS[9]  += e * v2.y;
                accS[10] += e * v2.z; accS[11] += e * v2.w;
                accS[12] += e * v3.x; accS[13] += e * v3.y;
                accS[14] += e * v3.z; accS[15] += e * v3.w;
            }
        } else if (doW) {
            for (int j = jlo; j <= jhi; ++j) {
                float e = __expf(myScRow[j] - mU);
                const float4* vrj = (const float4*)(Vt + j * 68) + d16 * 4;
                float4 v0 = vrj[0], v1 = vrj[1], v2 = vrj[2], v3 = vrj[3];
                lW += e;
                accW[0]  += e * v0.x; accW[1]  += e * v0.y;
                accW[2]  += e * v0.z; accW[3]  += e * v0.w;
                accW[4]  += e * v1.x; accW[5]  += e * v1.y;
                accW[6]  += e * v1.z; accW[7]  += e * v1.w;
                accW[8]  += e * v2.x; accW[9]  += e * v2.y;
                accW[10] += e * v2.z; accW[11] += e * v2.w;
                accW[12] += e * v3.x; accW[13] += e * v3.y;
                accW[14] += e * v3.z; accW[15] += e * v3.w;
            }
        }
    }

    // ---- combine with kernel-2 result and store ----
    const float invS = gate0 / fmaxf(lS, 1e-20f);
    const float invW = gate1 / fmaxf(lW, 1e-20f);
    float4* orow = (float4*)(out + (s * HQ + hkv * GQA + h) * DIM);
    #pragma unroll
    for (int r = 0; r < 4; ++r) {
        float4 o = orow[d16 * 4 + r];
        o.x += invS * accS[r * 4 + 0] + invW * accW[r * 4 + 0];
        o.y += invS * accS[r * 4 + 1] + invW * accW[r * 4 + 1];
        o.z += invS * accS[r * 4 + 2] + invW * accW[r * 4 + 2];
        o.w += invS * accS[r * 4 + 3] + invW * accW[r * 4 + 3];
        orow[d16 * 4 + r] = o;
    }
}

// ---------------------------------------------------------------------------
extern "C" void kernel_launch(void* const* d_in, const int* in_sizes, int n_in,
                              void* d_out, int out_size)
{
    const float* q  = (const float*)d_in[0];
    const float* k  = (const float*)d_in[1];
    const float* v  = (const float*)d_in[2];
    const float* wk = (const float*)d_in[3];
    const float* wv = (const float*)d_in[4];
    const float* wg = (const float*)d_in[5];
    float* out = (float*)d_out;

    compress_kernel<<<64, NT>>>(k, v, wk, wv);
    cmp_kernel<<<(S_LEN / QT) * HKV, NT>>>(q, wg, out);

    const size_t smem_bytes = 13056 * sizeof(float);
    cudaFuncSetAttribute(branch_kernel,
                         cudaFuncAttributeMaxDynamicSharedMemorySize, (int)smem_bytes);
    branch_kernel<<<(S_LEN / QT) * HKV, NT, smem_bytes>>>(q, k, v, wg, out);
}

// round 5
// speedup vs baseline: 1.7197x; 1.5836x over previous
#include <cuda_runtime.h>

#define S_LEN  2048
#define HKV    2
#define HQ     16
#define GQA    8
#define DIM    64
#define LC     32
#define CSTRIDE 16
#define LB     64
#define KSEL   8
#define WIN    512
#define SC_N   127
#define NOUT   31
#define SCALE  0.125f
#define QT     8
#define NT     256

__device__ float g_ck[HKV * SC_N * DIM];
__device__ float g_cv[HKV * SC_N * DIM];
__device__ unsigned g_selmask[HKV * S_LEN];

__device__ __forceinline__ float dot4(float4 a, float4 b) {
    return a.x * b.x + a.y * b.y + a.z * b.z + a.w * b.w;
}

// ---------------------------------------------------------------------------
// conv1d compressor: block = (hkv, group of 2 compressed positions)
// ---------------------------------------------------------------------------
__global__ void __launch_bounds__(256) compress_kernel(
    const float* __restrict__ k, const float* __restrict__ v,
    const float* __restrict__ wk, const float* __restrict__ wv)
{
    const int hkv = blockIdx.x & 1;
    const int c0  = (blockIdx.x >> 1) * 2;
    __shared__ float ks[48 * 64];
    __shared__ float vs[48 * 64];
    __shared__ float red[8 * 64];
    const int tid = threadIdx.x;

    for (int idx = tid; idx < 48 * 16; idx += NT) {
        int row = idx >> 4, quad = idx & 15;
        int pos = c0 * CSTRIDE + row;
        float4 kk = make_float4(0.f, 0.f, 0.f, 0.f);
        float4 vv = kk;
        if (pos < S_LEN) {
            kk = __ldg((const float4*)(k + (pos * HKV + hkv) * DIM) + quad);
            vv = __ldg((const float4*)(v + (pos * HKV + hkv) * DIM) + quad);
        }
        ((float4*)(ks + row * 64))[quad] = kk;
        ((float4*)(vs + row * 64))[quad] = vv;
    }
    __syncthreads();

    const int o    = tid & 63;
    const int part = tid >> 6;
    float ak[2] = {0.f, 0.f};
    float av[2] = {0.f, 0.f};
    for (int i = part * 16; i < part * 16 + 16; ++i) {
        const float4* wk4 = (const float4*)(wk + (o * DIM + i) * LC);
        const float4* wv4 = (const float4*)(wv + (o * DIM + i) * LC);
        #pragma unroll
        for (int t4 = 0; t4 < 8; ++t4) {
            float4 a  = __ldg(&wk4[t4]);
            float4 bw = __ldg(&wv4[t4]);
            int t = t4 * 4;
            #pragma unroll
            for (int cc = 0; cc < 2; ++cc) {
                const float* kr = ks + (cc * 16 + t) * 64 + i;
                const float* vr = vs + (cc * 16 + t) * 64 + i;
                ak[cc] += a.x  * kr[0] + a.y  * kr[64] + a.z  * kr[128] + a.w  * kr[192];
                av[cc] += bw.x * vr[0] + bw.y * vr[64] + bw.z * vr[128] + bw.w * vr[192];
            }
        }
    }
    #pragma unroll
    for (int cc = 0; cc < 2; ++cc) red[(part * 2 + cc) * 64 + o] = ak[cc];
    __syncthreads();
    if (part == 0) {
        #pragma unroll
        for (int cc = 0; cc < 2; ++cc)
            if (c0 + cc < SC_N)
                g_ck[(hkv * SC_N + c0 + cc) * DIM + o] =
                    red[cc * 64 + o] + red[(2 + cc) * 64 + o]
                  + red[(4 + cc) * 64 + o] + red[(6 + cc) * 64 + o];
    }
    __syncthreads();
    #pragma unroll
    for (int cc = 0; cc < 2; ++cc) red[(part * 2 + cc) * 64 + o] = av[cc];
    __syncthreads();
    if (part == 0) {
        #pragma unroll
        for (int cc = 0; cc < 2; ++cc)
            if (c0 + cc < SC_N)
                g_cv[(hkv * SC_N + c0 + cc) * DIM + o] =
                    red[cc * 64 + o] + red[(2 + cc) * 64 + o]
                  + red[(4 + cc) * 64 + o] + red[(6 + cc) * 64 + o];
    }
}

// ---------------------------------------------------------------------------
// Kernel 2: compressed attention + block selection (unchanged structure).
// ---------------------------------------------------------------------------
__global__ void __launch_bounds__(256) cmp_kernel(
    const float* __restrict__ q, const float* __restrict__ wg,
    float* __restrict__ out)
{
    __shared__ float scq[QT * 8 * 132];
    __shared__ float pkvA[QT * 128];

    const int bx   = blockIdx.x;
    const int hkv  = bx & 1;
    const int s0   = (bx >> 1) * QT;
    const int tid  = threadIdx.x;
    const int lane = tid & 31;
    const int warp = tid >> 5;
    const int s    = s0 + warp;
    const int h    = lane >> 2;
    const int d16  = lane & 3;

    const float4* qrow = (const float4*)(q + (s * HQ + hkv * GQA + h) * DIM);
    float4 qf[4];
    #pragma unroll
    for (int r = 0; r < 4; ++r) qf[r] = __ldg(&qrow[d16 * 4 + r]);

    float g2;
    {
        const float4* wrow = (const float4*)(wg + 2 * DIM);
        float a = 0.f;
        #pragma unroll
        for (int r = 0; r < 4; ++r) a += dot4(qf[r], __ldg(&wrow[d16 * 4 + r]));
        a += __shfl_xor_sync(~0u, a, 1);
        a += __shfl_xor_sync(~0u, a, 2);
        g2 = a;
    }

    const int Nc = (s >= 31) ? (((s - 31) >> 4) + 1) : 0;
    const float* ckb = g_ck + hkv * SC_N * DIM;
    const float* cvb = g_cv + hkv * SC_N * DIM;

    for (int c = 0; c < Nc; ++c) {
        const float4* kr = (const float4*)(ckb + c * DIM);
        float a = 0.f;
        #pragma unroll
        for (int r = 0; r < 4; ++r) a += dot4(qf[r], __ldg(&kr[d16 * 4 + r]));
        a += __shfl_xor_sync(~0u, a, 1);
        a += __shfl_xor_sync(~0u, a, 2);
        if (d16 == 0) scq[(warp * 8 + h) * 132 + c] = a * SCALE;
    }
    __syncwarp();

    for (int hh = 0; hh < 8; ++hh) {
        float* row = scq + (warp * 8 + hh) * 132;
        float m = -1e30f;
        for (int c = lane; c < Nc; c += 32) m = fmaxf(m, row[c]);
        #pragma unroll
        for (int off = 16; off; off >>= 1) m = fmaxf(m, __shfl_xor_sync(~0u, m, off));
        float sum = 0.f;
        for (int c = lane; c < Nc; c += 32) {
            float p = expf(row[c] - m);
            row[c] = p; sum += p;
        }
        #pragma unroll
        for (int off = 16; off; off >>= 1) sum += __shfl_xor_sync(~0u, sum, off);
        float inv = (sum > 0.f) ? (1.f / sum) : 0.f;
        for (int c = lane; c < 128; c += 32)
            row[c] = (c < Nc) ? row[c] * inv : 0.f;
    }
    __syncwarp();

    for (int c = lane; c < 128; c += 32) {
        float a = 0.f;
        #pragma unroll
        for (int hh = 0; hh < 8; ++hh) a += scq[(warp * 8 + hh) * 132 + c];
        pkvA[warp * 128 + c] = a;
    }
    __syncwarp();

    {
        float myval;
        if (lane < NOUT) {
            const float* pv = pkvA + warp * 128 + lane * 4;
            myval = (pv[0] + pv[1] + pv[2] + pv[3] + pv[4]) / 5.0f;
        } else {
            myval = -1.0f;
        }
        if (lane == (s >> 6)) myval = __int_as_float(0x7f800000);
        unsigned mask = 0;
        #pragma unroll
        for (int r = 0; r < KSEL; ++r) {
            float bv = myval; int bi = lane;
            #pragma unroll
            for (int off = 16; off; off >>= 1) {
                float ov = __shfl_xor_sync(~0u, bv, off);
                int   oi = __shfl_xor_sync(~0u, bi, off);
                if (ov > bv || (ov == bv && oi < bi)) { bv = ov; bi = oi; }
            }
            mask |= 1u << bi;
            if (lane == bi) myval = __int_as_float(0xff800000);
        }
        if (lane == 0) g_selmask[hkv * S_LEN + s] = mask;
    }

    float acc[16];
    #pragma unroll
    for (int i = 0; i < 16; ++i) acc[i] = 0.f;
    for (int c = 0; c < Nc; ++c) {
        float p = scq[(warp * 8 + h) * 132 + c];
        const float4* vr = (const float4*)(cvb + c * DIM);
        #pragma unroll
        for (int r = 0; r < 4; ++r) {
            float4 t = __ldg(&vr[d16 * 4 + r]);
            acc[r * 4 + 0] += p * t.x; acc[r * 4 + 1] += p * t.y;
            acc[r * 4 + 2] += p * t.z; acc[r * 4 + 3] += p * t.w;
        }
    }
    float4* orow = (float4*)(out + (s * HQ + hkv * GQA + h) * DIM);
    #pragma unroll
    for (int r = 0; r < 4; ++r)
        orow[d16 * 4 + r] = make_float4(g2 * acc[r * 4],     g2 * acc[r * 4 + 1],
                                        g2 * acc[r * 4 + 2], g2 * acc[r * 4 + 3]);
}

// ---------------------------------------------------------------------------
// Kernel 3: sel + swa branches. Score pass: lane owns keys {lane, lane+32} x 8h.
// PV pass: lane owns (h = lane>>2, d16 = lane&3).
// smem: Kt[64*68] Vt[64*68] qs[8*8*68] probs[8*8*68] = 69632 B dynamic.
// ---------------------------------------------------------------------------
extern __shared__ float pool3[];

__global__ void __launch_bounds__(256) branch_kernel(
    const float* __restrict__ q, const float* __restrict__ k,
    const float* __restrict__ v, const float* __restrict__ wg,
    float* __restrict__ out)
{
    __shared__ unsigned selmaskSh[QT];
    __shared__ unsigned cmbShared;

    float* Kt    = pool3;            // [64][68]
    float* Vt    = pool3 + 4352;     // [64][68]
    float* qs    = pool3 + 8704;     // [QT][8][68]
    float* probs = pool3 + 13056;    // [QT][8][68]

    const int bx   = blockIdx.x;
    const int hkv  = bx & 1;
    const int s0   = (bx >> 1) * QT;
    const int tid  = threadIdx.x;
    const int lane = tid & 31;
    const int warp = tid >> 5;
    const int s    = s0 + warp;
    const int h    = lane >> 2;
    const int d16  = lane & 3;

    // load q fragment, compute gates, stage q into per-warp smem
    float gate0, gate1;
    {
        const float4* qrow = (const float4*)(q + (s * HQ + hkv * GQA + h) * DIM);
        float4 qf[4];
        #pragma unroll
        for (int r = 0; r < 4; ++r) qf[r] = __ldg(&qrow[d16 * 4 + r]);
        #pragma unroll
        for (int e = 0; e < 2; ++e) {
            const float4* wrow = (const float4*)(wg + e * DIM);
            float a = 0.f;
            #pragma unroll
            for (int r = 0; r < 4; ++r) a += dot4(qf[r], __ldg(&wrow[d16 * 4 + r]));
            a += __shfl_xor_sync(~0u, a, 1);
            a += __shfl_xor_sync(~0u, a, 2);
            if (e == 0) gate0 = a; else gate1 = a;
        }
        float4* qdst = (float4*)(qs + warp * 544 + h * 68);
        #pragma unroll
        for (int r = 0; r < 4; ++r) qdst[d16 * 4 + r] = qf[r];
    }

    if (lane == 0) selmaskSh[warp] = g_selmask[hkv * S_LEN + s];
    __syncthreads();
    if (tid == 0) {
        unsigned cmb = 0;
        #pragma unroll
        for (int qq = 0; qq < QT; ++qq) cmb |= selmaskSh[qq];
        int loS = s0 - (WIN - 1); if (loS < 0) loS = 0;
        int lowBlk = loS >> 6;
        int hiBlk  = (s0 + QT - 1) >> 6;
        unsigned wmask = (hiBlk >= 31 ? 0xFFFFFFFFu : ((1u << (hiBlk + 1)) - 1u))
                       & ~((1u << lowBlk) - 1u);
        cmbShared = cmb | wmask;
    }
    __syncthreads();

    const unsigned selMine = selmaskSh[warp];
    unsigned rem = cmbShared;

    float accS[16], accW[16];
    #pragma unroll
    for (int i = 0; i < 16; ++i) { accS[i] = 0.f; accW[i] = 0.f; }
    float mU = -1e30f, lS = 0.f, lW = 0.f;
    const int winLo = s - (WIN - 1);
    float* probsW = probs + warp * 544;
    const float4* qq4 = (const float4*)(qs + warp * 544);

    while (rem) {
        int b = __ffs(rem) - 1;
        rem &= rem - 1;
        const int base = b * LB;

        __syncthreads();
        for (int idx = tid; idx < 1024; idx += NT) {
            int row = idx >> 4, quad = idx & 15;
            int pos = base + row;
            ((float4*)(Kt + row * 68))[quad] =
                __ldg((const float4*)(k + (pos * HKV + hkv) * DIM) + quad);
            ((float4*)(Vt + row * 68))[quad] =
                __ldg((const float4*)(v + (pos * HKV + hkv) * DIM) + quad);
        }
        __syncthreads();

        if (base > s) continue;
        const bool selAct = (selMine >> b) & 1u;
        const bool swaAct = (base + 63) >= winLo;
        if (!(selAct || swaAct)) continue;

        // ---- score pass: lane owns keys j1=lane, j2=lane+32, all 8 heads ----
        float sc1[8], sc2[8];
        #pragma unroll
        for (int hh = 0; hh < 8; ++hh) { sc1[hh] = 0.f; sc2[hh] = 0.f; }
        {
            const float4* kA = (const float4*)Kt + lane * 17;
            const float4* kB = kA + 32 * 17;
            #pragma unroll
            for (int d4 = 0; d4 < 16; ++d4) {
                float4 a = kA[d4];
                float4 bb = kB[d4];
                #pragma unroll
                for (int hh = 0; hh < 8; ++hh) {
                    float4 qv = qq4[hh * 17 + d4];
                    sc1[hh] += dot4(qv, a);
                    sc2[hh] += dot4(qv, bb);
                }
            }
        }

        const int jhi  = min(63, s - base);
        const int pos1 = base + lane;
        const int pos2 = pos1 + 32;
        const bool c1 = (lane <= jhi);
        const bool c2 = (lane + 32 <= jhi);
        const bool w1 = c1 && (pos1 >= winLo);
        const bool w2 = c2 && (pos2 >= winLo);

        float tS = -1e30f, tW = -1e30f;
        #pragma unroll
        for (int hh = 0; hh < 8; ++hh) {
            sc1[hh] *= SCALE; sc2[hh] *= SCALE;
            if (c1) { tS = fmaxf(tS, sc1[hh]); if (w1) tW = fmaxf(tW, sc1[hh]); }
            if (c2) { tS = fmaxf(tS, sc2[hh]); if (w2) tW = fmaxf(tW, sc2[hh]); }
        }
        #pragma unroll
        for (int off = 16; off; off >>= 1) {
            tS = fmaxf(tS, __shfl_xor_sync(~0u, tS, off));
            tW = fmaxf(tW, __shfl_xor_sync(~0u, tW, off));
        }

        const bool doS = selAct;
        const bool doW = swaAct && (tW > -1e29f);
        float t = -1e30f;
        if (doS) t = tS;
        if (doW) t = fmaxf(t, tW);
        if (t > mU) {
            float f = __expf(mU - t);
            lS *= f; lW *= f;
            #pragma unroll
            for (int i = 0; i < 16; ++i) { accS[i] *= f; accW[i] *= f; }
            mU = t;
        }

        // exp + write probs (only valid j's are read back)
        if (c1) {
            #pragma unroll
            for (int hh = 0; hh < 8; ++hh)
                probsW[hh * 68 + lane] = __expf(sc1[hh] - mU);
        }
        if (c2) {
            #pragma unroll
            for (int hh = 0; hh < 8; ++hh)
                probsW[hh * 68 + lane + 32] = __expf(sc2[hh] - mU);
        }
        __syncwarp();

        // ---- PV pass: lane owns (h, d16) ----
        const float* pRow = probsW + h * 68;
        const int jlo = max(0, winLo - base);
        if (doS && doW) {
            #pragma unroll 2
            for (int j = 0; j <= jhi; ++j) {
                float p = pRow[j];
                const float4* vrj = (const float4*)(Vt + j * 68) + d16 * 4;
                float4 v0 = vrj[0], v1 = vrj[1], v2 = vrj[2], v3 = vrj[3];
                lS += p;
                accS[0]  += p * v0.x; accS[1]  += p * v0.y;
                accS[2]  += p * v0.z; accS[3]  += p * v0.w;
                accS[4]  += p * v1.x; accS[5]  += p * v1.y;
                accS[6]  += p * v1.z; accS[7]  += p * v1.w;
                accS[8]  += p * v2.x; accS[9]  += p * v2.y;
                accS[10] += p * v2.z; accS[11] += p * v2.w;
                accS[12] += p * v3.x; accS[13] += p * v3.y;
                accS[14] += p * v3.z; accS[15] += p * v3.w;
                if (j >= jlo) {
                    lW += p;
                    accW[0]  += p * v0.x; accW[1]  += p * v0.y;
                    accW[2]  += p * v0.z; accW[3]  += p * v0.w;
                    accW[4]  += p * v1.x; accW[5]  += p * v1.y;
                    accW[6]  += p * v1.z; accW[7]  += p * v1.w;
                    accW[8]  += p * v2.x; accW[9]  += p * v2.y;
                    accW[10] += p * v2.z; accW[11] += p * v2.w;
                    accW[12] += p * v3.x; accW[13] += p * v3.y;
                    accW[14] += p * v3.z; accW[15] += p * v3.w;
                }
            }
        } else if (doS) {
            #pragma unroll 2
            for (int j = 0; j <= jhi; ++j) {
                float p = pRow[j];
                const float4* vrj = (const float4*)(Vt + j * 68) + d16 * 4;
                float4 v0 = vrj[0], v1 = vrj[1], v2 = vrj[2], v3 = vrj[3];
                lS += p;
                accS[0]  += p * v0.x; accS[1]  += p * v0.y;
                accS[2]  += p * v0.z; accS[3]  += p * v0.w;
                accS[4]  += p * v1.x; accS[5]  += p * v1.y;
                accS[6]  += p * v1.z; accS[7]  += p * v1.w;
                accS[8]  += p * v2.x; accS[9]  += p * v2.y;
                accS[10] += p * v2.z; accS[11] += p * v2.w;
                accS[12] += p * v3.x; accS[13] += p * v3.y;
                accS[14] += p * v3.z; accS[15] += p * v3.w;
            }
        } else {
            #pragma unroll 2
            for (int j = jlo; j <= jhi; ++j) {
                float p = pRow[j];
                const float4* vrj = (const float4*)(Vt + j * 68) + d16 * 4;
                float4 v0 = vrj[0], v1 = vrj[1], v2 = vrj[2], v3 = vrj[3];
                lW += p;
                accW[0]  += p * v0.x; accW[1]  += p * v0.y;
                accW[2]  += p * v0.z; accW[3]  += p * v0.w;
                accW[4]  += p * v1.x; accW[5]  += p * v1.y;
                accW[6]  += p * v1.z; accW[7]  += p * v1.w;
                accW[8]  += p * v2.x; accW[9]  += p * v2.y;
                accW[10] += p * v2.z; accW[11] += p * v2.w;
                accW[12] += p * v3.x; accW[13] += p * v3.y;
                accW[14] += p * v3.z; accW[15] += p * v3.w;
            }
        }
    }

    const float invS = gate0 / fmaxf(lS, 1e-20f);
    const float invW = gate1 / fmaxf(lW, 1e-20f);
    float4* orow = (float4*)(out + (s * HQ + hkv * GQA + h) * DIM);
    #pragma unroll
    for (int r = 0; r < 4; ++r) {
        float4 o = orow[d16 * 4 + r];
        o.x += invS * accS[r * 4 + 0] + invW * accW[r * 4 + 0];
        o.y += invS * accS[r * 4 + 1] + invW * accW[r * 4 + 1];
        o.z += invS * accS[r * 4 + 2] + invW * accW[r * 4 + 2];
        o.w += invS * accS[r * 4 + 3] + invW * accW[r * 4 + 3];
        orow[d16 * 4 + r] = o;
    }
}

// ---------------------------------------------------------------------------
extern "C" void kernel_launch(void* const* d_in, const int* in_sizes, int n_in,
                              void* d_out, int out_size)
{
    const float* q  = (const float*)d_in[0];
    const float* k  = (const float*)d_in[1];
    const float* v  = (const float*)d_in[2];
    const float* wk = (const float*)d_in[3];
    const float* wv = (const float*)d_in[4];
    const float* wg = (const float*)d_in[5];
    float* out = (float*)d_out;

    compress_kernel<<<128, NT>>>(k, v, wk, wv);
    cmp_kernel<<<(S_LEN / QT) * HKV, NT>>>(q, wg, out);

    const size_t smem_bytes = 17408 * sizeof(float);
    cudaFuncSetAttribute(branch_kernel,
                         cudaFuncAttributeMaxDynamicSharedMemorySize, (int)smem_bytes);
    branch_kernel<<<(S_LEN / QT) * HKV, NT, smem_bytes>>>(q, k, v, wg, out);
}

// round 6
// speedup vs baseline: 1.8414x; 1.0707x over previous
#include <cuda_runtime.h>

#define S_LEN  2048
#define HKV    2
#define HQ     16
#define GQA    8
#define DIM    64
#define LC     32
#define CSTRIDE 16
#define LB     64
#define KSEL   8
#define WIN    512
#define SC_N   127
#define NOUT   31
#define SCALE  0.125f
#define QT     8
#define NT     256

typedef unsigned long long u64t;

__device__ float g_ck[HKV * SC_N * DIM];
__device__ float g_cv[HKV * SC_N * DIM];
__device__ unsigned g_selmask[HKV * S_LEN];

__device__ __forceinline__ float dot4(float4 a, float4 b) {
    return a.x * b.x + a.y * b.y + a.z * b.z + a.w * b.w;
}
__device__ __forceinline__ void ffma2(u64t& d, u64t a, u64t b) {
    asm("fma.rn.f32x2 %0, %1, %2, %0;" : "+l"(d) : "l"(a), "l"(b));
}
__device__ __forceinline__ void mul2(u64t& d, u64t a, u64t b) {
    asm("mul.rn.f32x2 %0, %1, %2;" : "=l"(d) : "l"(a), "l"(b));
}
__device__ __forceinline__ void add2(u64t& d, u64t a, u64t b) {
    asm("add.rn.f32x2 %0, %1, %2;" : "=l"(d) : "l"(a), "l"(b));
}
__device__ __forceinline__ u64t pack2(float lo, float hi) {
    u64t r; asm("mov.b64 %0, {%1, %2};" : "=l"(r) : "f"(lo), "f"(hi)); return r;
}
__device__ __forceinline__ float2 unpack2(u64t a) {
    float2 r; asm("mov.b64 {%0, %1}, %2;" : "=f"(r.x), "=f"(r.y) : "l"(a)); return r;
}

// ---------------------------------------------------------------------------
// conv1d compressor: block = (hkv, k-or-v, group of 8 compressed positions)
// ---------------------------------------------------------------------------
__global__ void __launch_bounds__(256) compress_kernel(
    const float* __restrict__ k, const float* __restrict__ v,
    const float* __restrict__ wk, const float* __restrict__ wv)
{
    const int b   = blockIdx.x;         // 64 blocks
    const int hkv = b & 1;
    const int isV = (b >> 1) & 1;
    const int c0  = (b >> 2) * 8;       // 0,8,...,120
    const float* src = isV ? v : k;
    const float* w   = isV ? wv : wk;
    float* dst = isV ? g_cv : g_ck;

    __shared__ float xs[144 * 64];
    __shared__ float red[4][8][64];
    const int tid = threadIdx.x;

    for (int idx = tid; idx < 144 * 16; idx += NT) {
        int row = idx >> 4, quad = idx & 15;
        int pos = c0 * CSTRIDE + row;
        float4 val = make_float4(0.f, 0.f, 0.f, 0.f);
        if (pos < S_LEN)
            val = __ldg((const float4*)(src + (pos * HKV + hkv) * DIM) + quad);
        ((float4*)(xs + row * 64))[quad] = val;
    }
    __syncthreads();

    const int o    = tid & 63;
    const int part = tid >> 6;
    float acc[8];
    #pragma unroll
    for (int cc = 0; cc < 8; ++cc) acc[cc] = 0.f;

    for (int i = part * 16; i < part * 16 + 16; ++i) {
        const float4* w4 = (const float4*)(w + (o * DIM + i) * LC);
        #pragma unroll
        for (int t4 = 0; t4 < 8; ++t4) {
            float4 a = __ldg(&w4[t4]);
            int t = t4 * 4;
            #pragma unroll
            for (int cc = 0; cc < 8; ++cc) {
                const float* xr = xs + (cc * 16 + t) * 64 + i;
                acc[cc] += a.x * xr[0] + a.y * xr[64] + a.z * xr[128] + a.w * xr[192];
            }
        }
    }
    #pragma unroll
    for (int cc = 0; cc < 8; ++cc) red[part][cc][o] = acc[cc];
    __syncthreads();
    if (part == 0) {
        #pragma unroll
        for (int cc = 0; cc < 8; ++cc)
            if (c0 + cc < SC_N)
                dst[(hkv * SC_N + c0 + cc) * DIM + o] =
                    red[0][cc][o] + red[1][cc][o] + red[2][cc][o] + red[3][cc][o];
    }
}

// ---------------------------------------------------------------------------
// Kernel 2: compressed attention + block selection.
// ---------------------------------------------------------------------------
__global__ void __launch_bounds__(256) cmp_kernel(
    const float* __restrict__ q, const float* __restrict__ wg,
    float* __restrict__ out)
{
    __shared__ float scq[QT * 8 * 132];
    __shared__ float pkvA[QT * 128];

    const int bx   = blockIdx.x;
    const int hkv  = bx & 1;
    const int s0   = (bx >> 1) * QT;
    const int tid  = threadIdx.x;
    const int lane = tid & 31;
    const int warp = tid >> 5;
    const int s    = s0 + warp;
    const int h    = lane >> 2;
    const int d16  = lane & 3;

    const float4* qrow = (const float4*)(q + (s * HQ + hkv * GQA + h) * DIM);
    float4 qf[4];
    #pragma unroll
    for (int r = 0; r < 4; ++r) qf[r] = __ldg(&qrow[d16 * 4 + r]);
    u64t uq[8];
    #pragma unroll
    for (int r = 0; r < 4; ++r) {
        uq[2 * r]     = pack2(qf[r].x, qf[r].y);
        uq[2 * r + 1] = pack2(qf[r].z, qf[r].w);
    }

    float g2;
    {
        const float4* wrow = (const float4*)(wg + 2 * DIM);
        float a = 0.f;
        #pragma unroll
        for (int r = 0; r < 4; ++r) a += dot4(qf[r], __ldg(&wrow[d16 * 4 + r]));
        a += __shfl_xor_sync(~0u, a, 1);
        a += __shfl_xor_sync(~0u, a, 2);
        g2 = a;
    }

    const int Nc = (s >= 31) ? (((s - 31) >> 4) + 1) : 0;
    const float* ckb = g_ck + hkv * SC_N * DIM;
    const float* cvb = g_cv + hkv * SC_N * DIM;

    for (int c = 0; c < Nc; ++c) {
        const ulonglong2* kr2 = (const ulonglong2*)(ckb + c * DIM) + d16 * 4;
        u64t a2 = 0ull;
        #pragma unroll
        for (int r = 0; r < 4; ++r) {
            ulonglong2 t = __ldg(&kr2[r]);
            ffma2(a2, uq[2 * r], t.x);
            ffma2(a2, uq[2 * r + 1], t.y);
        }
        float2 f = unpack2(a2);
        float a = f.x + f.y;
        a += __shfl_xor_sync(~0u, a, 1);
        a += __shfl_xor_sync(~0u, a, 2);
        if (d16 == 0) scq[(warp * 8 + h) * 132 + c] = a * SCALE;
    }
    __syncwarp();

    // exact softmax per head (probs feed top-k selection)
    for (int hh = 0; hh < 8; ++hh) {
        float* row = scq + (warp * 8 + hh) * 132;
        float m = -1e30f;
        for (int c = lane; c < Nc; c += 32) m = fmaxf(m, row[c]);
        #pragma unroll
        for (int off = 16; off; off >>= 1) m = fmaxf(m, __shfl_xor_sync(~0u, m, off));
        float sum = 0.f;
        for (int c = lane; c < Nc; c += 32) {
            float p = expf(row[c] - m);
            row[c] = p; sum += p;
        }
        #pragma unroll
        for (int off = 16; off; off >>= 1) sum += __shfl_xor_sync(~0u, sum, off);
        float inv = (sum > 0.f) ? (1.f / sum) : 0.f;
        for (int c = lane; c < 128; c += 32)
            row[c] = (c < Nc) ? row[c] * inv : 0.f;
    }
    __syncwarp();

    for (int c = lane; c < 128; c += 32) {
        float a = 0.f;
        #pragma unroll
        for (int hh = 0; hh < 8; ++hh) a += scq[(warp * 8 + hh) * 132 + c];
        pkvA[warp * 128 + c] = a;
    }
    __syncwarp();

    {
        float myval;
        if (lane < NOUT) {
            const float* pv = pkvA + warp * 128 + lane * 4;
            myval = (pv[0] + pv[1] + pv[2] + pv[3] + pv[4]) / 5.0f;
        } else {
            myval = -1.0f;
        }
        if (lane == (s >> 6)) myval = __int_as_float(0x7f800000);
        unsigned mask = 0;
        #pragma unroll
        for (int r = 0; r < KSEL; ++r) {
            float bv = myval; int bi = lane;
            #pragma unroll
            for (int off = 16; off; off >>= 1) {
                float ov = __shfl_xor_sync(~0u, bv, off);
                int   oi = __shfl_xor_sync(~0u, bi, off);
                if (ov > bv || (ov == bv && oi < bi)) { bv = ov; bi = oi; }
            }
            mask |= 1u << bi;
            if (lane == bi) myval = __int_as_float(0xff800000);
        }
        if (lane == 0) g_selmask[hkv * S_LEN + s] = mask;
    }

    u64t acc2[8];
    #pragma unroll
    for (int i = 0; i < 8; ++i) acc2[i] = 0ull;
    for (int c = 0; c < Nc; ++c) {
        float p = scq[(warp * 8 + h) * 132 + c];
        u64t p2 = pack2(p, p);
        const ulonglong2* vr2 = (const ulonglong2*)(cvb + c * DIM) + d16 * 4;
        #pragma unroll
        for (int r = 0; r < 4; ++r) {
            ulonglong2 t = __ldg(&vr2[r]);
            ffma2(acc2[2 * r], p2, t.x);
            ffma2(acc2[2 * r + 1], p2, t.y);
        }
    }
    float4* orow = (float4*)(out + (s * HQ + hkv * GQA + h) * DIM);
    #pragma unroll
    for (int r = 0; r < 4; ++r) {
        float2 lo = unpack2(acc2[2 * r]);
        float2 hi = unpack2(acc2[2 * r + 1]);
        orow[d16 * 4 + r] = make_float4(g2 * lo.x, g2 * lo.y, g2 * hi.x, g2 * hi.y);
    }
}

// ---------------------------------------------------------------------------
// Kernel 3: sel + swa. Score: lane owns keys {lane, lane+32} x 8h, packed FFMA2.
// PV: lane owns (h, d16), packed accumulators, accT trick for dual tiles.
// ---------------------------------------------------------------------------
extern __shared__ float pool3[];

__global__ void __launch_bounds__(256) branch_kernel(
    const float* __restrict__ q, const float* __restrict__ k,
    const float* __restrict__ v, const float* __restrict__ wg,
    float* __restrict__ out)
{
    __shared__ unsigned selmaskSh[QT];
    __shared__ unsigned cmbShared;

    float* Kt    = pool3;            // [64][68]
    float* Vt    = pool3 + 4352;     // [64][68]
    float* qs    = pool3 + 8704;     // [QT][8][68]
    float* probs = pool3 + 13056;    // [QT][8][68]

    const int bx   = blockIdx.x;
    const int hkv  = bx & 1;
    const int s0   = (bx >> 1) * QT;
    const int tid  = threadIdx.x;
    const int lane = tid & 31;
    const int warp = tid >> 5;
    const int s    = s0 + warp;
    const int h    = lane >> 2;
    const int d16  = lane & 3;

    float gate0, gate1;
    {
        const float4* qrow = (const float4*)(q + (s * HQ + hkv * GQA + h) * DIM);
        float4 qf[4];
        #pragma unroll
        for (int r = 0; r < 4; ++r) qf[r] = __ldg(&qrow[d16 * 4 + r]);
        #pragma unroll
        for (int e = 0; e < 2; ++e) {
            const float4* wrow = (const float4*)(wg + e * DIM);
            float a = 0.f;
            #pragma unroll
            for (int r = 0; r < 4; ++r) a += dot4(qf[r], __ldg(&wrow[d16 * 4 + r]));
            a += __shfl_xor_sync(~0u, a, 1);
            a += __shfl_xor_sync(~0u, a, 2);
            if (e == 0) gate0 = a; else gate1 = a;
        }
        float4* qdst = (float4*)(qs + warp * 544 + h * 68);
        #pragma unroll
        for (int r = 0; r < 4; ++r) qdst[d16 * 4 + r] = qf[r];
    }

    if (lane == 0) selmaskSh[warp] = g_selmask[hkv * S_LEN + s];
    __syncthreads();
    if (tid == 0) {
        unsigned cmb = 0;
        #pragma unroll
        for (int qq = 0; qq < QT; ++qq) cmb |= selmaskSh[qq];
        int loS = s0 - (WIN - 1); if (loS < 0) loS = 0;
        int lowBlk = loS >> 6;
        int hiBlk  = (s0 + QT - 1) >> 6;
        unsigned wmask = (hiBlk >= 31 ? 0xFFFFFFFFu : ((1u << (hiBlk + 1)) - 1u))
                       & ~((1u << lowBlk) - 1u);
        cmbShared = cmb | wmask;
    }
    __syncthreads();

    const unsigned selMine = selmaskSh[warp];
    unsigned rem = cmbShared;

    u64t accS2[8], accW2[8];
    #pragma unroll
    for (int i = 0; i < 8; ++i) { accS2[i] = 0ull; accW2[i] = 0ull; }
    float mU = -1e30f, lS = 0.f, lW = 0.f;
    const int winLo = s - (WIN - 1);
    float* probsW = probs + warp * 544;
    const ulonglong2* qq2 = (const ulonglong2*)(qs + warp * 544);

    while (rem) {
        int b = __ffs(rem) - 1;
        rem &= rem - 1;
        const int base = b * LB;

        __syncthreads();
        for (int idx = tid; idx < 1024; idx += NT) {
            int row = idx >> 4, quad = idx & 15;
            int pos = base + row;
            ((float4*)(Kt + row * 68))[quad] =
                __ldg((const float4*)(k + (pos * HKV + hkv) * DIM) + quad);
            ((float4*)(Vt + row * 68))[quad] =
                __ldg((const float4*)(v + (pos * HKV + hkv) * DIM) + quad);
        }
        __syncthreads();

        if (base > s) continue;
        const bool selAct = (selMine >> b) & 1u;
        const bool swaAct = (base + 63) >= winLo;
        if (!(selAct || swaAct)) continue;

        // ---- score pass: packed over dims ----
        u64t s1[8], s2[8];
        #pragma unroll
        for (int hh = 0; hh < 8; ++hh) { s1[hh] = 0ull; s2[hh] = 0ull; }
        {
            const ulonglong2* kA = (const ulonglong2*)Kt + lane * 17;
            const ulonglong2* kB = kA + 32 * 17;
            #pragma unroll
            for (int d4 = 0; d4 < 16; ++d4) {
                ulonglong2 a = kA[d4];
                ulonglong2 bb = kB[d4];
                #pragma unroll
                for (int hh = 0; hh < 8; ++hh) {
                    ulonglong2 qv = qq2[hh * 17 + d4];
                    ffma2(s1[hh], qv.x, a.x);
                    ffma2(s1[hh], qv.y, a.y);
                    ffma2(s2[hh], qv.x, bb.x);
                    ffma2(s2[hh], qv.y, bb.y);
                }
            }
        }

        const int jhi  = min(63, s - base);
        const int pos1 = base + lane;
        const bool c1 = (lane <= jhi);
        const bool c2 = (lane + 32 <= jhi);
        const bool w1 = c1 && (pos1 >= winLo);
        const bool w2 = c2 && (pos1 + 32 >= winLo);

        float sc1[8], sc2[8];
        float tS = -1e30f, tW = -1e30f;
        #pragma unroll
        for (int hh = 0; hh < 8; ++hh) {
            float2 f1 = unpack2(s1[hh]);
            float2 f2 = unpack2(s2[hh]);
            sc1[hh] = (f1.x + f1.y) * SCALE;
            sc2[hh] = (f2.x + f2.y) * SCALE;
            if (c1) { tS = fmaxf(tS, sc1[hh]); if (w1) tW = fmaxf(tW, sc1[hh]); }
            if (c2) { tS = fmaxf(tS, sc2[hh]); if (w2) tW = fmaxf(tW, sc2[hh]); }
        }
        #pragma unroll
        for (int off = 16; off; off >>= 1) {
            tS = fmaxf(tS, __shfl_xor_sync(~0u, tS, off));
            tW = fmaxf(tW, __shfl_xor_sync(~0u, tW, off));
        }

        const bool doS = selAct;
        const bool doW = swaAct && (tW > -1e29f);
        float t = -1e30f;
        if (doS) t = tS;
        if (doW) t = fmaxf(t, tW);
        if (t > mU) {
            float f = __expf(mU - t);
            u64t f2p = pack2(f, f);
            lS *= f; lW *= f;
            #pragma unroll
            for (int i = 0; i < 8; ++i) {
                mul2(accS2[i], accS2[i], f2p);
                mul2(accW2[i], accW2[i], f2p);
            }
            mU = t;
        }

        if (c1) {
            #pragma unroll
            for (int hh = 0; hh < 8; ++hh)
                probsW[hh * 68 + lane] = __expf(sc1[hh] - mU);
        }
        if (c2) {
            #pragma unroll
            for (int hh = 0; hh < 8; ++hh)
                probsW[hh * 68 + lane + 32] = __expf(sc2[hh] - mU);
        }
        __syncwarp();

        // ---- PV pass ----
        const float* pRow = probsW + h * 68;
        const ulonglong2* vb = (const ulonglong2*)Vt + d16 * 4;
        const int jlo = max(0, winLo - base);

        if (doS && doW) {
            // pre-window part -> sel only
            for (int j = 0; j < jlo; ++j) {
                float p = pRow[j];
                u64t p2 = pack2(p, p);
                const ulonglong2* vj = vb + j * 17;
                ulonglong2 v0 = vj[0], v1 = vj[1], v2 = vj[2], v3 = vj[3];
                lS += p;
                ffma2(accS2[0], p2, v0.x); ffma2(accS2[1], p2, v0.y);
                ffma2(accS2[2], p2, v1.x); ffma2(accS2[3], p2, v1.y);
                ffma2(accS2[4], p2, v2.x); ffma2(accS2[5], p2, v2.y);
                ffma2(accS2[6], p2, v3.x); ffma2(accS2[7], p2, v3.y);
            }
            // window part -> temp, added to both
            u64t accT2[8];
            #pragma unroll
            for (int i = 0; i < 8; ++i) accT2[i] = 0ull;
            float lT = 0.f;
            for (int j = jlo; j <= jhi; ++j) {
                float p = pRow[j];
                u64t p2 = pack2(p, p);
                const ulonglong2* vj = vb + j * 17;
                ulonglong2 v0 = vj[0], v1 = vj[1], v2 = vj[2], v3 = vj[3];
                lT += p;
                ffma2(accT2[0], p2, v0.x); ffma2(accT2[1], p2, v0.y);
                ffma2(accT2[2], p2, v1.x); ffma2(accT2[3], p2, v1.y);
                ffma2(accT2[4], p2, v2.x); ffma2(accT2[5], p2, v2.y);
                ffma2(accT2[6], p2, v3.x); ffma2(accT2[7], p2, v3.y);
            }
            lS += lT; lW += lT;
            #pragma unroll
            for (int i = 0; i < 8; ++i) {
                add2(accS2[i], accS2[i], accT2[i]);
                add2(accW2[i], accW2[i], accT2[i]);
            }
        } else if (doS) {
            for (int j = 0; j <= jhi; ++j) {
                float p = pRow[j];
                u64t p2 = pack2(p, p);
                const ulonglong2* vj = vb + j * 17;
                ulonglong2 v0 = vj[0], v1 = vj[1], v2 = vj[2], v3 = vj[3];
                lS += p;
                ffma2(accS2[0], p2, v0.x); ffma2(accS2[1], p2, v0.y);
                ffma2(accS2[2], p2, v1.x); ffma2(accS2[3], p2, v1.y);
                ffma2(accS2[4], p2, v2.x); ffma2(accS2[5], p2, v2.y);
                ffma2(accS2[6], p2, v3.x); ffma2(accS2[7], p2, v3.y);
            }
        } else if (doW) {
            for (int j = jlo; j <= jhi; ++j) {
                float p = pRow[j];
                u64t p2 = pack2(p, p);
                const ulonglong2* vj = vb + j * 17;
                ulonglong2 v0 = vj[0], v1 = vj[1], v2 = vj[2], v3 = vj[3];
                lW += p;
                ffma2(accW2[0], p2, v0.x); ffma2(accW2[1], p2, v0.y);
                ffma2(accW2[2], p2, v1.x); ffma2(accW2[3], p2, v1.y);
                ffma2(accW2[4], p2, v2.x); ffma2(accW2[5], p2, v2.y);
                ffma2(accW2[6], p2, v3.x); ffma2(accW2[7], p2, v3.y);
            }
        }
    }

    const float invS = gate0 / fmaxf(lS, 1e-20f);
    const float invW = gate1 / fmaxf(lW, 1e-20f);
    float4* orow = (float4*)(out + (s * HQ + hkv * GQA + h) * DIM);
    #pragma unroll
    for (int r = 0; r < 4; ++r) {
        float2 sLo = unpack2(accS2[2 * r]);
        float2 sHi = unpack2(accS2[2 * r + 1]);
        float2 wLo = unpack2(accW2[2 * r]);
        float2 wHi = unpack2(accW2[2 * r + 1]);
        float4 o = orow[d16 * 4 + r];
        o.x += invS * sLo.x + invW * wLo.x;
        o.y += invS * sLo.y + invW * wLo.y;
        o.z += invS * sHi.x + invW * wHi.x;
        o.w += invS * sHi.y + invW * wHi.y;
        orow[d16 * 4 + r] = o;
    }
}

// ---------------------------------------------------------------------------
extern "C" void kernel_launch(void* const* d_in, const int* in_sizes, int n_in,
                              void* d_out, int out_size)
{
    const float* q  = (const float*)d_in[0];
    const float* k  = (const float*)d_in[1];
    const float* v  = (const float*)d_in[2];
    const float* wk = (const float*)d_in[3];
    const float* wv = (const float*)d_in[4];
    const float* wg = (const float*)d_in[5];
    float* out = (float*)d_out;

    compress_kernel<<<64, NT>>>(k, v, wk, wv);
    cmp_kernel<<<(S_LEN / QT) * HKV, NT>>>(q, wg, out);

    const size_t smem_bytes = 17408 * sizeof(float);
    cudaFuncSetAttribute(branch_kernel,
                         cudaFuncAttributeMaxDynamicSharedMemorySize, (int)smem_bytes);
    branch_kernel<<<(S_LEN / QT) * HKV, NT, smem_bytes>>>(q, k, v, wg, out);
}

// round 7
// speedup vs baseline: 1.9202x; 1.0428x over previous
#include <cuda_runtime.h>
#include <cstdint>

#define S_LEN  2048
#define HKV    2
#define HQ     16
#define GQA    8
#define DIM    64
#define LC     32
#define CSTRIDE 16
#define LB     64
#define KSEL   8
#define WIN    512
#define SC_N   127
#define NOUT   31
#define SCALE  0.125f
#define QT     8
#define NT     256

typedef unsigned long long u64t;

__device__ float g_ck[HKV * SC_N * DIM];
__device__ float g_cv[HKV * SC_N * DIM];
__device__ unsigned g_selmask[HKV * S_LEN];

__device__ __forceinline__ float dot4(float4 a, float4 b) {
    return a.x * b.x + a.y * b.y + a.z * b.z + a.w * b.w;
}
__device__ __forceinline__ void ffma2(u64t& d, u64t a, u64t b) {
    asm("fma.rn.f32x2 %0, %1, %2, %0;" : "+l"(d) : "l"(a), "l"(b));
}
__device__ __forceinline__ void mul2(u64t& d, u64t a, u64t b) {
    asm("mul.rn.f32x2 %0, %1, %2;" : "=l"(d) : "l"(a), "l"(b));
}
__device__ __forceinline__ void add2(u64t& d, u64t a, u64t b) {
    asm("add.rn.f32x2 %0, %1, %2;" : "=l"(d) : "l"(a), "l"(b));
}
__device__ __forceinline__ u64t pack2(float lo, float hi) {
    u64t r; asm("mov.b64 %0, {%1, %2};" : "=l"(r) : "f"(lo), "f"(hi)); return r;
}
__device__ __forceinline__ float2 unpack2(u64t a) {
    float2 r; asm("mov.b64 {%0, %1}, %2;" : "=f"(r.x), "=f"(r.y) : "l"(a)); return r;
}
__device__ __forceinline__ void cp16(void* sdst, const void* gsrc) {
    uint32_t sa = (uint32_t)__cvta_generic_to_shared(sdst);
    asm volatile("cp.async.cg.shared.global [%0], [%1], 16;" :: "r"(sa), "l"(gsrc));
}
#define CP_COMMIT() asm volatile("cp.async.commit_group;")
#define CP_WAIT0()  asm volatile("cp.async.wait_group 0;")

// ---------------------------------------------------------------------------
// conv1d compressor: block = (hkv, k/v, 8 compressed positions, o-half)
// ---------------------------------------------------------------------------
__global__ void __launch_bounds__(256) compress_kernel(
    const float* __restrict__ k, const float* __restrict__ v,
    const float* __restrict__ wk, const float* __restrict__ wv)
{
    const int b     = blockIdx.x;        // 128 blocks
    const int hkv   = b & 1;
    const int isV   = (b >> 1) & 1;
    const int ohalf = (b >> 2) & 1;
    const int c0    = (b >> 3) * 8;      // 0,8,...,120
    const float* src = isV ? v : k;
    const float* w   = isV ? wv : wk;
    float* dst = isV ? g_cv : g_ck;

    __shared__ float xs[144 * 64];
    __shared__ float red[8 * 8 * 32];
    const int tid = threadIdx.x;

    for (int idx = tid; idx < 144 * 16; idx += NT) {
        int row = idx >> 4, quad = idx & 15;
        int pos = c0 * CSTRIDE + row;
        float4 val = make_float4(0.f, 0.f, 0.f, 0.f);
        if (pos < S_LEN)
            val = __ldg((const float4*)(src + (pos * HKV + hkv) * DIM) + quad);
        ((float4*)(xs + row * 64))[quad] = val;
    }
    __syncthreads();

    const int ol   = tid & 31;           // local o
    const int o    = ohalf * 32 + ol;
    const int part = tid >> 5;           // 0..7, i range of 8
    float acc[8];
    #pragma unroll
    for (int cc = 0; cc < 8; ++cc) acc[cc] = 0.f;

    for (int i = part * 8; i < part * 8 + 8; ++i) {
        const float4* w4 = (const float4*)(w + (o * DIM + i) * LC);
        #pragma unroll
        for (int t4 = 0; t4 < 8; ++t4) {
            float4 a = __ldg(&w4[t4]);
            int t = t4 * 4;
            #pragma unroll
            for (int cc = 0; cc < 8; ++cc) {
                const float* xr = xs + (cc * 16 + t) * 64 + i;
                acc[cc] += a.x * xr[0] + a.y * xr[64] + a.z * xr[128] + a.w * xr[192];
            }
        }
    }
    #pragma unroll
    for (int cc = 0; cc < 8; ++cc) red[(part * 8 + cc) * 32 + ol] = acc[cc];
    __syncthreads();
    if (part == 0) {
        #pragma unroll
        for (int cc = 0; cc < 8; ++cc) {
            if (c0 + cc < SC_N) {
                float a = 0.f;
                #pragma unroll
                for (int p = 0; p < 8; ++p) a += red[(p * 8 + cc) * 32 + ol];
                dst[(hkv * SC_N + c0 + cc) * DIM + o] = a;
            }
        }
    }
}

// ---------------------------------------------------------------------------
// Kernel 2: compressed attention + block selection.
// ---------------------------------------------------------------------------
__global__ void __launch_bounds__(256) cmp_kernel(
    const float* __restrict__ q, const float* __restrict__ wg,
    float* __restrict__ out)
{
    __shared__ float scq[QT * 8 * 132];
    __shared__ float pkvA[QT * 128];

    const int bx   = blockIdx.x;
    const int hkv  = bx & 1;
    const int s0   = (bx >> 1) * QT;
    const int tid  = threadIdx.x;
    const int lane = tid & 31;
    const int warp = tid >> 5;
    const int s    = s0 + warp;
    const int h    = lane >> 2;
    const int d16  = lane & 3;

    const float4* qrow = (const float4*)(q + (s * HQ + hkv * GQA + h) * DIM);
    float4 qf[4];
    #pragma unroll
    for (int r = 0; r < 4; ++r) qf[r] = __ldg(&qrow[d16 * 4 + r]);
    u64t uq[8];
    #pragma unroll
    for (int r = 0; r < 4; ++r) {
        uq[2 * r]     = pack2(qf[r].x, qf[r].y);
        uq[2 * r + 1] = pack2(qf[r].z, qf[r].w);
    }

    float g2;
    {
        const float4* wrow = (const float4*)(wg + 2 * DIM);
        float a = 0.f;
        #pragma unroll
        for (int r = 0; r < 4; ++r) a += dot4(qf[r], __ldg(&wrow[d16 * 4 + r]));
        a += __shfl_xor_sync(~0u, a, 1);
        a += __shfl_xor_sync(~0u, a, 2);
        g2 = a;
    }

    const int Nc = (s >= 31) ? (((s - 31) >> 4) + 1) : 0;
    const float* ckb = g_ck + hkv * SC_N * DIM;
    const float* cvb = g_cv + hkv * SC_N * DIM;

    #pragma unroll 4
    for (int c = 0; c < Nc; ++c) {
        const ulonglong2* kr2 = (const ulonglong2*)(ckb + c * DIM) + d16 * 4;
        u64t a2 = 0ull;
        #pragma unroll
        for (int r = 0; r < 4; ++r) {
            ulonglong2 t = __ldg(&kr2[r]);
            ffma2(a2, uq[2 * r], t.x);
            ffma2(a2, uq[2 * r + 1], t.y);
        }
        float2 f = unpack2(a2);
        float a = f.x + f.y;
        a += __shfl_xor_sync(~0u, a, 1);
        a += __shfl_xor_sync(~0u, a, 2);
        if (d16 == 0) scq[(warp * 8 + h) * 132 + c] = a * SCALE;
    }
    __syncwarp();

    // exact softmax per head (probs feed top-k selection)
    for (int hh = 0; hh < 8; ++hh) {
        float* row = scq + (warp * 8 + hh) * 132;
        float m = -1e30f;
        for (int c = lane; c < Nc; c += 32) m = fmaxf(m, row[c]);
        #pragma unroll
        for (int off = 16; off; off >>= 1) m = fmaxf(m, __shfl_xor_sync(~0u, m, off));
        float sum = 0.f;
        for (int c = lane; c < Nc; c += 32) {
            float p = expf(row[c] - m);
            row[c] = p; sum += p;
        }
        #pragma unroll
        for (int off = 16; off; off >>= 1) sum += __shfl_xor_sync(~0u, sum, off);
        float inv = (sum > 0.f) ? (1.f / sum) : 0.f;
        for (int c = lane; c < 128; c += 32)
            row[c] = (c < Nc) ? row[c] * inv : 0.f;
    }
    __syncwarp();

    for (int c = lane; c < 128; c += 32) {
        float a = 0.f;
        #pragma unroll
        for (int hh = 0; hh < 8; ++hh) a += scq[(warp * 8 + hh) * 132 + c];
        pkvA[warp * 128 + c] = a;
    }
    __syncwarp();

    {
        float myval;
        if (lane < NOUT) {
            const float* pv = pkvA + warp * 128 + lane * 4;
            myval = (pv[0] + pv[1] + pv[2] + pv[3] + pv[4]) / 5.0f;
        } else {
            myval = -1.0f;
        }
        if (lane == (s >> 6)) myval = __int_as_float(0x7f800000);
        unsigned mask = 0;
        #pragma unroll
        for (int r = 0; r < KSEL; ++r) {
            float bv = myval; int bi = lane;
            #pragma unroll
            for (int off = 16; off; off >>= 1) {
                float ov = __shfl_xor_sync(~0u, bv, off);
                int   oi = __shfl_xor_sync(~0u, bi, off);
                if (ov > bv || (ov == bv && oi < bi)) { bv = ov; bi = oi; }
            }
            mask |= 1u << bi;
            if (lane == bi) myval = __int_as_float(0xff800000);
        }
        if (lane == 0) g_selmask[hkv * S_LEN + s] = mask;
    }

    u64t acc2[8];
    #pragma unroll
    for (int i = 0; i < 8; ++i) acc2[i] = 0ull;
    #pragma unroll 2
    for (int c = 0; c < Nc; ++c) {
        float p = scq[(warp * 8 + h) * 132 + c];
        u64t p2 = pack2(p, p);
        const ulonglong2* vr2 = (const ulonglong2*)(cvb + c * DIM) + d16 * 4;
        #pragma unroll
        for (int r = 0; r < 4; ++r) {
            ulonglong2 t = __ldg(&vr2[r]);
            ffma2(acc2[2 * r], p2, t.x);
            ffma2(acc2[2 * r + 1], p2, t.y);
        }
    }
    float4* orow = (float4*)(out + (s * HQ + hkv * GQA + h) * DIM);
    #pragma unroll
    for (int r = 0; r < 4; ++r) {
        float2 lo = unpack2(acc2[2 * r]);
        float2 hi = unpack2(acc2[2 * r + 1]);
        orow[d16 * 4 + r] = make_float4(g2 * lo.x, g2 * lo.y, g2 * hi.x, g2 * hi.y);
    }
}

// ---------------------------------------------------------------------------
// Kernel 3: sel + swa with double-buffered cp.async pipeline.
// smem pool: stage0 K|V [8704], stage1 K|V [8704], qs [4352], probs [4352]
// ---------------------------------------------------------------------------
extern __shared__ float pool3[];

__device__ __forceinline__ void stage_issue(
    const float* __restrict__ k, const float* __restrict__ v,
    int hkv, int base, float* buf, int tid)
{
    float* Kd = buf;
    float* Vd = buf + 4352;
    #pragma unroll
    for (int r = 0; r < 4; ++r) {
        int idx = tid + r * NT;              // 0..1023
        int row = idx >> 4, quad = idx & 15;
        int pos = base + row;
        const float4* gk = (const float4*)(k + (pos * HKV + hkv) * DIM) + quad;
        const float4* gv = (const float4*)(v + (pos * HKV + hkv) * DIM) + quad;
        cp16(Kd + row * 68 + quad * 4, gk);
        cp16(Vd + row * 68 + quad * 4, gv);
    }
}

__global__ void __launch_bounds__(256) branch_kernel(
    const float* __restrict__ q, const float* __restrict__ k,
    const float* __restrict__ v, const float* __restrict__ wg,
    float* __restrict__ out)
{
    __shared__ unsigned selmaskSh[QT];
    __shared__ int blkList[32];
    __shared__ int nblkSh;

    float* qs    = pool3 + 17408;    // [QT][8][68]
    float* probs = pool3 + 21760;    // [QT][8][68]

    const int bx   = blockIdx.x;
    const int hkv  = bx & 1;
    const int s0   = (bx >> 1) * QT;
    const int tid  = threadIdx.x;
    const int lane = tid & 31;
    const int warp = tid >> 5;
    const int s    = s0 + warp;
    const int h    = lane >> 2;
    const int d16  = lane & 3;

    float gate0, gate1;
    {
        const float4* qrow = (const float4*)(q + (s * HQ + hkv * GQA + h) * DIM);
        float4 qf[4];
        #pragma unroll
        for (int r = 0; r < 4; ++r) qf[r] = __ldg(&qrow[d16 * 4 + r]);
        #pragma unroll
        for (int e = 0; e < 2; ++e) {
            const float4* wrow = (const float4*)(wg + e * DIM);
            float a = 0.f;
            #pragma unroll
            for (int r = 0; r < 4; ++r) a += dot4(qf[r], __ldg(&wrow[d16 * 4 + r]));
            a += __shfl_xor_sync(~0u, a, 1);
            a += __shfl_xor_sync(~0u, a, 2);
            if (e == 0) gate0 = a; else gate1 = a;
        }
        float4* qdst = (float4*)(qs + warp * 544 + h * 68);
        #pragma unroll
        for (int r = 0; r < 4; ++r) qdst[d16 * 4 + r] = qf[r];
    }

    if (lane == 0) selmaskSh[warp] = g_selmask[hkv * S_LEN + s];
    __syncthreads();
    if (tid == 0) {
        unsigned cmb = 0;
        #pragma unroll
        for (int qq = 0; qq < QT; ++qq) cmb |= selmaskSh[qq];
        int loS = s0 - (WIN - 1); if (loS < 0) loS = 0;
        int lowBlk = loS >> 6;
        int hiBlk  = (s0 + QT - 1) >> 6;
        unsigned wmask = (hiBlk >= 31 ? 0xFFFFFFFFu : ((1u << (hiBlk + 1)) - 1u))
                       & ~((1u << lowBlk) - 1u);
        unsigned m = cmb | wmask;
        int n = 0;
        while (m) { int bb = __ffs(m) - 1; m &= m - 1; blkList[n++] = bb; }
        nblkSh = n;
    }
    __syncthreads();

    const unsigned selMine = selmaskSh[warp];
    const int nblk = nblkSh;

    u64t accS2[8], accW2[8];
    #pragma unroll
    for (int i = 0; i < 8; ++i) { accS2[i] = 0ull; accW2[i] = 0ull; }
    float mU = -1e30f, lS = 0.f, lW = 0.f;
    const int winLo = s - (WIN - 1);
    float* probsW = probs + warp * 544;
    const ulonglong2* qq2 = (const ulonglong2*)(qs + warp * 544);

    // prologue: prefetch first tile
    stage_issue(k, v, hkv, blkList[0] * LB, pool3, tid);
    CP_COMMIT();

    for (int it = 0; it < nblk; ++it) {
        CP_WAIT0();
        __syncthreads();
        if (it + 1 < nblk) {
            stage_issue(k, v, hkv, blkList[it + 1] * LB, pool3 + ((it + 1) & 1) * 8704, tid);
            CP_COMMIT();
        }
        const float* Kt = pool3 + (it & 1) * 8704;
        const float* Vt = Kt + 4352;
        const int b = blkList[it];
        const int base = b * LB;

        if (base > s) continue;
        const bool selAct = (selMine >> b) & 1u;
        const bool swaAct = (base + 63) >= winLo;
        if (!(selAct || swaAct)) continue;

        // ---- score pass: lane owns keys {lane, lane+32} x 8 heads, packed ----
        u64t s1[8], s2[8];
        #pragma unroll
        for (int hh = 0; hh < 8; ++hh) { s1[hh] = 0ull; s2[hh] = 0ull; }
        {
            const ulonglong2* kA = (const ulonglong2*)Kt + lane * 17;
            const ulonglong2* kB = kA + 32 * 17;
            #pragma unroll
            for (int d4 = 0; d4 < 16; ++d4) {
                ulonglong2 a = kA[d4];
                ulonglong2 bb = kB[d4];
                #pragma unroll
                for (int hh = 0; hh < 8; ++hh) {
                    ulonglong2 qv = qq2[hh * 17 + d4];
                    ffma2(s1[hh], qv.x, a.x);
                    ffma2(s1[hh], qv.y, a.y);
                    ffma2(s2[hh], qv.x, bb.x);
                    ffma2(s2[hh], qv.y, bb.y);
                }
            }
        }

        const int jhi  = min(63, s - base);
        const int pos1 = base + lane;
        const bool c1 = (lane <= jhi);
        const bool c2 = (lane + 32 <= jhi);
        const bool w1 = c1 && (pos1 >= winLo);
        const bool w2 = c2 && (pos1 + 32 >= winLo);

        float sc1[8], sc2[8];
        float tS = -1e30f, tW = -1e30f;
        #pragma unroll
        for (int hh = 0; hh < 8; ++hh) {
            float2 f1 = unpack2(s1[hh]);
            float2 f2 = unpack2(s2[hh]);
            sc1[hh] = (f1.x + f1.y) * SCALE;
            sc2[hh] = (f2.x + f2.y) * SCALE;
            if (c1) { tS = fmaxf(tS, sc1[hh]); if (w1) tW = fmaxf(tW, sc1[hh]); }
            if (c2) { tS = fmaxf(tS, sc2[hh]); if (w2) tW = fmaxf(tW, sc2[hh]); }
        }
        #pragma unroll
        for (int off = 16; off; off >>= 1) {
            tS = fmaxf(tS, __shfl_xor_sync(~0u, tS, off));
            tW = fmaxf(tW, __shfl_xor_sync(~0u, tW, off));
        }

        const bool doS = selAct;
        const bool doW = swaAct && (tW > -1e29f);
        float t = -1e30f;
        if (doS) t = tS;
        if (doW) t = fmaxf(t, tW);
        if (t > mU) {
            float f = __expf(mU - t);
            u64t f2p = pack2(f, f);
            lS *= f; lW *= f;
            #pragma unroll
            for (int i = 0; i < 8; ++i) {
                mul2(accS2[i], accS2[i], f2p);
                mul2(accW2[i], accW2[i], f2p);
            }
            mU = t;
        }

        if (c1) {
            #pragma unroll
            for (int hh = 0; hh < 8; ++hh)
                probsW[hh * 68 + lane] = __expf(sc1[hh] - mU);
        }
        if (c2) {
            #pragma unroll
            for (int hh = 0; hh < 8; ++hh)
                probsW[hh * 68 + lane + 32] = __expf(sc2[hh] - mU);
        }
        __syncwarp();

        // ---- PV pass: lane owns (h, d16) ----
        const float* pRow = probsW + h * 68;
        const ulonglong2* vb = (const ulonglong2*)Vt + d16 * 4;
        const int jlo = max(0, winLo - base);

        if (doS && doW) {
            for (int j = 0; j < jlo; ++j) {
                float p = pRow[j];
                u64t p2 = pack2(p, p);
                const ulonglong2* vj = vb + j * 17;
                ulonglong2 v0 = vj[0], v1 = vj[1], v2 = vj[2], v3 = vj[3];
                lS += p;
                ffma2(accS2[0], p2, v0.x); ffma2(accS2[1], p2, v0.y);
                ffma2(accS2[2], p2, v1.x); ffma2(accS2[3], p2, v1.y);
                ffma2(accS2[4], p2, v2.x); ffma2(accS2[5], p2, v2.y);
                ffma2(accS2[6], p2, v3.x); ffma2(accS2[7], p2, v3.y);
            }
            u64t accT2[8];
            #pragma unroll
            for (int i = 0; i < 8; ++i) accT2[i] = 0ull;
            float lT = 0.f;
            for (int j = jlo; j <= jhi; ++j) {
                float p = pRow[j];
                u64t p2 = pack2(p, p);
                const ulonglong2* vj = vb + j * 17;
                ulonglong2 v0 = vj[0], v1 = vj[1], v2 = vj[2], v3 = vj[3];
                lT += p;
                ffma2(accT2[0], p2, v0.x); ffma2(accT2[1], p2, v0.y);
                ffma2(accT2[2], p2, v1.x); ffma2(accT2[3], p2, v1.y);
                ffma2(accT2[4], p2, v2.x); ffma2(accT2[5], p2, v2.y);
                ffma2(accT2[6], p2, v3.x); ffma2(accT2[7], p2, v3.y);
            }
            lS += lT; lW += lT;
            #pragma unroll
            for (int i = 0; i < 8; ++i) {
                add2(accS2[i], accS2[i], accT2[i]);
                add2(accW2[i], accW2[i], accT2[i]);
            }
        } else if (doS) {
            for (int j = 0; j <= jhi; ++j) {
                float p = pRow[j];
                u64t p2 = pack2(p, p);
                const ulonglong2* vj = vb + j * 17;
                ulonglong2 v0 = vj[0], v1 = vj[1], v2 = vj[2], v3 = vj[3];
                lS += p;
                ffma2(accS2[0], p2, v0.x); ffma2(accS2[1], p2, v0.y);
                ffma2(accS2[2], p2, v1.x); ffma2(accS2[3], p2, v1.y);
                ffma2(accS2[4], p2, v2.x); ffma2(accS2[5], p2, v2.y);
                ffma2(accS2[6], p2, v3.x); ffma2(accS2[7], p2, v3.y);
            }
        } else if (doW) {
            for (int j = jlo; j <= jhi; ++j) {
                float p = pRow[j];
                u64t p2 = pack2(p, p);
                const ulonglong2* vj = vb + j * 17;
                ulonglong2 v0 = vj[0], v1 = vj[1], v2 = vj[2], v3 = vj[3];
                lW += p;
                ffma2(accW2[0], p2, v0.x); ffma2(accW2[1], p2, v0.y);
                ffma2(accW2[2], p2, v1.x); ffma2(accW2[3], p2, v1.y);
                ffma2(accW2[4], p2, v2.x); ffma2(accW2[5], p2, v2.y);
                ffma2(accW2[6], p2, v3.x); ffma2(accW2[7], p2, v3.y);
            }
        }
    }

    const float invS = gate0 / fmaxf(lS, 1e-20f);
    const float invW = gate1 / fmaxf(lW, 1e-20f);
    float4* orow = (float4*)(out + (s * HQ + hkv * GQA + h) * DIM);
    #pragma unroll
    for (int r = 0; r < 4; ++r) {
        float2 sLo = unpack2(accS2[2 * r]);
        float2 sHi = unpack2(accS2[2 * r + 1]);
        float2 wLo = unpack2(accW2[2 * r]);
        float2 wHi = unpack2(accW2[2 * r + 1]);
        float4 o = orow[d16 * 4 + r];
        o.x += invS * sLo.x + invW * wLo.x;
        o.y += invS * sLo.y + invW * wLo.y;
        o.z += invS * sHi.x + invW * wHi.x;
        o.w += invS * sHi.y + invW * wHi.y;
        orow[d16 * 4 + r] = o;
    }
}

// ---------------------------------------------------------------------------
extern "C" void kernel_launch(void* const* d_in, const int* in_sizes, int n_in,
                              void* d_out, int out_size)
{
    const float* q  = (const float*)d_in[0];
    const float* k  = (const float*)d_in[1];
    const float* v  = (const float*)d_in[2];
    const float* wk = (const float*)d_in[3];
    const float* wv = (const float*)d_in[4];
    const float* wg = (const float*)d_in[5];
    float* out = (float*)d_out;

    compress_kernel<<<128, NT>>>(k, v, wk, wv);
    cmp_kernel<<<(S_LEN / QT) * HKV, NT>>>(q, wg, out);

    const size_t smem_bytes = 26112 * sizeof(float);   // 104448 B
    cudaFuncSetAttribute(branch_kernel,
                         cudaFuncAttributeMaxDynamicSharedMemorySize, (int)smem_bytes);
    branch_kernel<<<(S_LEN / QT) * HKV, NT, smem_bytes>>>(q, k, v, wg, out);
}

// round 8
// speedup vs baseline: 2.8818x; 1.5008x over previous
#include <cuda_runtime.h>
#include <cstdint>

#define S_LEN  2048
#define HKV    2
#define HQ     16
#define GQA    8
#define DIM    64
#define LC     32
#define CSTRIDE 16
#define LB     64
#define KSEL   8
#define WIN    512
#define SC_N   127
#define NOUT   31
#define SCALE  0.125f
#define QT     8
#define NT     256

typedef unsigned long long u64t;

__device__ float g_ck[HKV * SC_N * DIM];
__device__ float g_cv[HKV * SC_N * DIM];
__device__ unsigned g_selmask[HKV * S_LEN];

__device__ __forceinline__ float dot4(float4 a, float4 b) {
    return a.x * b.x + a.y * b.y + a.z * b.z + a.w * b.w;
}
__device__ __forceinline__ void ffma2(u64t& d, u64t a, u64t b) {
    asm("fma.rn.f32x2 %0, %1, %2, %0;" : "+l"(d) : "l"(a), "l"(b));
}
__device__ __forceinline__ void mul2(u64t& d, u64t a, u64t b) {
    asm("mul.rn.f32x2 %0, %1, %2;" : "=l"(d) : "l"(a), "l"(b));
}
__device__ __forceinline__ void add2(u64t& d, u64t a, u64t b) {
    asm("add.rn.f32x2 %0, %1, %2;" : "=l"(d) : "l"(a), "l"(b));
}
__device__ __forceinline__ u64t pack2(float lo, float hi) {
    u64t r; asm("mov.b64 %0, {%1, %2};" : "=l"(r) : "f"(lo), "f"(hi)); return r;
}
__device__ __forceinline__ float2 unpack2(u64t a) {
    float2 r; asm("mov.b64 {%0, %1}, %2;" : "=f"(r.x), "=f"(r.y) : "l"(a)); return r;
}
__device__ __forceinline__ void cp16(void* sdst, const void* gsrc) {
    uint32_t sa = (uint32_t)__cvta_generic_to_shared(sdst);
    asm volatile("cp.async.cg.shared.global [%0], [%1], 16;" :: "r"(sa), "l"(gsrc));
}
#define CP_COMMIT() asm volatile("cp.async.commit_group;")
#define CP_WAIT0()  asm volatile("cp.async.wait_group 0;")

// ---------------------------------------------------------------------------
// conv1d compressor: block = (hkv, k/v, o-quarter, 8 compressed positions)
// ---------------------------------------------------------------------------
__global__ void __launch_bounds__(256) compress_kernel(
    const float* __restrict__ k, const float* __restrict__ v,
    const float* __restrict__ wk, const float* __restrict__ wv)
{
    const int b     = blockIdx.x;        // 256 blocks
    const int hkv   = b & 1;
    const int isV   = (b >> 1) & 1;
    const int oq    = (b >> 2) & 3;
    const int c0    = (b >> 4) * 8;
    const float* src = isV ? v : k;
    const float* w   = isV ? wv : wk;
    float* dst = isV ? g_cv : g_ck;

    __shared__ float xs[144 * 64];
    __shared__ float red[16 * 8 * 16];
    const int tid = threadIdx.x;

    for (int idx = tid; idx < 144 * 16; idx += NT) {
        int row = idx >> 4, quad = idx & 15;
        int pos = c0 * CSTRIDE + row;
        float4 val = make_float4(0.f, 0.f, 0.f, 0.f);
        if (pos < S_LEN)
            val = __ldg((const float4*)(src + (pos * HKV + hkv) * DIM) + quad);
        ((float4*)(xs + row * 64))[quad] = val;
    }
    __syncthreads();

    const int ol   = tid & 15;
    const int o    = oq * 16 + ol;
    const int part = tid >> 4;           // 0..15, i range of 4
    float acc[8];
    #pragma unroll
    for (int cc = 0; cc < 8; ++cc) acc[cc] = 0.f;

    for (int i = part * 4; i < part * 4 + 4; ++i) {
        const float4* w4 = (const float4*)(w + (o * DIM + i) * LC);
        #pragma unroll
        for (int t4 = 0; t4 < 8; ++t4) {
            float4 a = __ldg(&w4[t4]);
            int t = t4 * 4;
            #pragma unroll
            for (int cc = 0; cc < 8; ++cc) {
                const float* xr = xs + (cc * 16 + t) * 64 + i;
                acc[cc] += a.x * xr[0] + a.y * xr[64] + a.z * xr[128] + a.w * xr[192];
            }
        }
    }
    #pragma unroll
    for (int cc = 0; cc < 8; ++cc) red[(part * 8 + cc) * 16 + ol] = acc[cc];
    __syncthreads();
    if (part == 0) {
        #pragma unroll
        for (int cc = 0; cc < 8; ++cc) {
            if (c0 + cc < SC_N) {
                float a = 0.f;
                #pragma unroll
                for (int p = 0; p < 16; ++p) a += red[(p * 8 + cc) * 16 + ol];
                dst[(hkv * SC_N + c0 + cc) * DIM + o] = a;
            }
        }
    }
}

// ---------------------------------------------------------------------------
// Kernel 2: compressed attention + block selection.
// ---------------------------------------------------------------------------
__global__ void __launch_bounds__(256) cmp_kernel(
    const float* __restrict__ q, const float* __restrict__ wg,
    float* __restrict__ out)
{
    __shared__ float scq[QT * 8 * 132];
    __shared__ float pkvA[QT * 128];

    const int bx   = blockIdx.x;
    const int hkv  = bx & 1;
    const int s0   = (bx >> 1) * QT;
    const int tid  = threadIdx.x;
    const int lane = tid & 31;
    const int warp = tid >> 5;
    const int s    = s0 + warp;
    const int h    = lane >> 2;
    const int d16  = lane & 3;

    const float4* qrow = (const float4*)(q + (s * HQ + hkv * GQA + h) * DIM);
    float4 qf[4];
    #pragma unroll
    for (int r = 0; r < 4; ++r) qf[r] = __ldg(&qrow[d16 * 4 + r]);
    u64t uq[8];
    #pragma unroll
    for (int r = 0; r < 4; ++r) {
        uq[2 * r]     = pack2(qf[r].x, qf[r].y);
        uq[2 * r + 1] = pack2(qf[r].z, qf[r].w);
    }

    float g2;
    {
        const float4* wrow = (const float4*)(wg + 2 * DIM);
        float a = 0.f;
        #pragma unroll
        for (int r = 0; r < 4; ++r) a += dot4(qf[r], __ldg(&wrow[d16 * 4 + r]));
        a += __shfl_xor_sync(~0u, a, 1);
        a += __shfl_xor_sync(~0u, a, 2);
        g2 = a;
    }

    const int Nc = (s >= 31) ? (((s - 31) >> 4) + 1) : 0;
    const float* ckb = g_ck + hkv * SC_N * DIM;
    const float* cvb = g_cv + hkv * SC_N * DIM;

    #pragma unroll 4
    for (int c = 0; c < Nc; ++c) {
        const ulonglong2* kr2 = (const ulonglong2*)(ckb + c * DIM) + d16 * 4;
        u64t a2 = 0ull;
        #pragma unroll
        for (int r = 0; r < 4; ++r) {
            ulonglong2 t = __ldg(&kr2[r]);
            ffma2(a2, uq[2 * r], t.x);
            ffma2(a2, uq[2 * r + 1], t.y);
        }
        float2 f = unpack2(a2);
        float a = f.x + f.y;
        a += __shfl_xor_sync(~0u, a, 1);
        a += __shfl_xor_sync(~0u, a, 2);
        if (d16 == 0) scq[(warp * 8 + h) * 132 + c] = a * SCALE;
    }
    __syncwarp();

    for (int hh = 0; hh < 8; ++hh) {
        float* row = scq + (warp * 8 + hh) * 132;
        float m = -1e30f;
        for (int c = lane; c < Nc; c += 32) m = fmaxf(m, row[c]);
        #pragma unroll
        for (int off = 16; off; off >>= 1) m = fmaxf(m, __shfl_xor_sync(~0u, m, off));
        float sum = 0.f;
        for (int c = lane; c < Nc; c += 32) {
            float p = expf(row[c] - m);
            row[c] = p; sum += p;
        }
        #pragma unroll
        for (int off = 16; off; off >>= 1) sum += __shfl_xor_sync(~0u, sum, off);
        float inv = (sum > 0.f) ? (1.f / sum) : 0.f;
        for (int c = lane; c < 128; c += 32)
            row[c] = (c < Nc) ? row[c] * inv : 0.f;
    }
    __syncwarp();

    for (int c = lane; c < 128; c += 32) {
        float a = 0.f;
        #pragma unroll
        for (int hh = 0; hh < 8; ++hh) a += scq[(warp * 8 + hh) * 132 + c];
        pkvA[warp * 128 + c] = a;
    }
    __syncwarp();

    {
        float myval;
        if (lane < NOUT) {
            const float* pv = pkvA + warp * 128 + lane * 4;
            myval = (pv[0] + pv[1] + pv[2] + pv[3] + pv[4]) / 5.0f;
        } else {
            myval = -1.0f;
        }
        if (lane == (s >> 6)) myval = __int_as_float(0x7f800000);
        unsigned mask = 0;
        #pragma unroll
        for (int r = 0; r < KSEL; ++r) {
            float bv = myval; int bi = lane;
            #pragma unroll
            for (int off = 16; off; off >>= 1) {
                float ov = __shfl_xor_sync(~0u, bv, off);
                int   oi = __shfl_xor_sync(~0u, bi, off);
                if (ov > bv || (ov == bv && oi < bi)) { bv = ov; bi = oi; }
            }
            mask |= 1u << bi;
            if (lane == bi) myval = __int_as_float(0xff800000);
        }
        if (lane == 0) g_selmask[hkv * S_LEN + s] = mask;
    }

    u64t acc2[8];
    #pragma unroll
    for (int i = 0; i < 8; ++i) acc2[i] = 0ull;
    #pragma unroll 2
    for (int c = 0; c < Nc; ++c) {
        float p = scq[(warp * 8 + h) * 132 + c];
        u64t p2 = pack2(p, p);
        const ulonglong2* vr2 = (const ulonglong2*)(cvb + c * DIM) + d16 * 4;
        #pragma unroll
        for (int r = 0; r < 4; ++r) {
            ulonglong2 t = __ldg(&vr2[r]);
            ffma2(acc2[2 * r], p2, t.x);
            ffma2(acc2[2 * r + 1], p2, t.y);
        }
    }
    float4* orow = (float4*)(out + (s * HQ + hkv * GQA + h) * DIM);
    #pragma unroll
    for (int r = 0; r < 4; ++r) {
        float2 lo = unpack2(acc2[2 * r]);
        float2 hi = unpack2(acc2[2 * r + 1]);
        orow[d16 * 4 + r] = make_float4(g2 * lo.x, g2 * lo.y, g2 * hi.x, g2 * hi.y);
    }
}

// ---------------------------------------------------------------------------
// Kernel 3: sel + swa. Score: lane owns keys {lane, lane+32} x 8h (q uniform).
// PV: lane owns dims (2*lane, 2*lane+1) for ALL 8 heads; P reads uniform.
// smem: stage0 K|V [8704], stage1 K|V [8704], qs [4352], probsT [QT*512]
// ---------------------------------------------------------------------------
extern __shared__ float pool3[];

__device__ __forceinline__ void stage_issue(
    const float* __restrict__ k, const float* __restrict__ v,
    int hkv, int base, float* buf, int tid)
{
    float* Kd = buf;
    float* Vd = buf + 4352;
    #pragma unroll
    for (int r = 0; r < 4; ++r) {
        int idx = tid + r * NT;
        int row = idx >> 4, quad = idx & 15;
        int pos = base + row;
        cp16(Kd + row * 68 + quad * 4, (const float4*)(k + (pos * HKV + hkv) * DIM) + quad);
        cp16(Vd + row * 68 + quad * 4, (const float4*)(v + (pos * HKV + hkv) * DIM) + quad);
    }
}

__global__ void __launch_bounds__(256) branch_kernel(
    const float* __restrict__ q, const float* __restrict__ k,
    const float* __restrict__ v, const float* __restrict__ wg,
    float* __restrict__ out)
{
    __shared__ unsigned selmaskSh[QT];
    __shared__ int blkList[32];
    __shared__ int nblkSh;

    float* qs     = pool3 + 17408;   // [QT][8][68]
    float* probsT = pool3 + 21760;   // [QT][64][8]

    const int bx   = blockIdx.x;
    const int hkv  = bx & 1;
    const int s0   = (bx >> 1) * QT;
    const int tid  = threadIdx.x;
    const int lane = tid & 31;
    const int warp = tid >> 5;
    const int s    = s0 + warp;

    float gate0, gate1;
    {
        const int h   = lane >> 2;
        const int d16 = lane & 3;
        const float4* qrow = (const float4*)(q + (s * HQ + hkv * GQA + h) * DIM);
        float4 qf[4];
        #pragma unroll
        for (int r = 0; r < 4; ++r) qf[r] = __ldg(&qrow[d16 * 4 + r]);
        #pragma unroll
        for (int e = 0; e < 2; ++e) {
            const float4* wrow = (const float4*)(wg + e * DIM);
            float a = 0.f;
            #pragma unroll
            for (int r = 0; r < 4; ++r) a += dot4(qf[r], __ldg(&wrow[d16 * 4 + r]));
            a += __shfl_xor_sync(~0u, a, 1);
            a += __shfl_xor_sync(~0u, a, 2);
            if (e == 0) gate0 = a; else gate1 = a;
        }
        float4* qdst = (float4*)(qs + warp * 544 + h * 68);
        #pragma unroll
        for (int r = 0; r < 4; ++r) qdst[d16 * 4 + r] = qf[r];
    }

    if (lane == 0) selmaskSh[warp] = g_selmask[hkv * S_LEN + s];
    __syncthreads();
    if (tid == 0) {
        unsigned cmb = 0;
        #pragma unroll
        for (int qq = 0; qq < QT; ++qq) cmb |= selmaskSh[qq];
        int loS = s0 - (WIN - 1); if (loS < 0) loS = 0;
        int lowBlk = loS >> 6;
        int hiBlk  = (s0 + QT - 1) >> 6;
        unsigned wmask = (hiBlk >= 31 ? 0xFFFFFFFFu : ((1u << (hiBlk + 1)) - 1u))
                       & ~((1u << lowBlk) - 1u);
        unsigned m = cmb | wmask;
        int n = 0;
        while (m) { int bb = __ffs(m) - 1; m &= m - 1; blkList[n++] = bb; }
        nblkSh = n;
    }
    __syncthreads();

    const unsigned selMine = selmaskSh[warp];
    const int nblk = nblkSh;

    u64t accS2[8], accW2[8], lsw2[8];
    #pragma unroll
    for (int i = 0; i < 8; ++i) { accS2[i] = 0ull; accW2[i] = 0ull; lsw2[i] = 0ull; }
    float mU = -1e30f;
    const int winLo = s - (WIN - 1);
    float* probsW = probsT + warp * 512;
    const ulonglong2* qq2 = (const ulonglong2*)(qs + warp * 544);

    stage_issue(k, v, hkv, blkList[0] * LB, pool3, tid);
    CP_COMMIT();

    for (int it = 0; it < nblk; ++it) {
        CP_WAIT0();
        __syncthreads();
        if (it + 1 < nblk) {
            stage_issue(k, v, hkv, blkList[it + 1] * LB, pool3 + ((it + 1) & 1) * 8704, tid);
            CP_COMMIT();
        }
        const float* Kt = pool3 + (it & 1) * 8704;
        const float* Vt = Kt + 4352;
        const int b = blkList[it];
        const int base = b * LB;

        if (base > s) continue;
        const bool selAct = (selMine >> b) & 1u;
        const bool swaAct = (base + 63) >= winLo;
        if (!(selAct || swaAct)) continue;

        // ---- score pass: packed FFMA2, q reads uniform ----
        u64t s1[8], s2[8];
        #pragma unroll
        for (int hh = 0; hh < 8; ++hh) { s1[hh] = 0ull; s2[hh] = 0ull; }
        {
            const ulonglong2* kA = (const ulonglong2*)Kt + lane * 17;
            const ulonglong2* kB = kA + 32 * 17;
            #pragma unroll
            for (int d4 = 0; d4 < 16; ++d4) {
                ulonglong2 a = kA[d4];
                ulonglong2 bb = kB[d4];
                #pragma unroll
                for (int hh = 0; hh < 8; ++hh) {
                    ulonglong2 qv = qq2[hh * 17 + d4];
                    ffma2(s1[hh], qv.x, a.x);
                    ffma2(s1[hh], qv.y, a.y);
                    ffma2(s2[hh], qv.x, bb.x);
                    ffma2(s2[hh], qv.y, bb.y);
                }
            }
        }

        const int jhi  = min(63, s - base);
        const int pos1 = base + lane;
        const bool c1 = (lane <= jhi);
        const bool c2 = (lane + 32 <= jhi);
        const bool w1 = c1 && (pos1 >= winLo);
        const bool w2 = c2 && (pos1 + 32 >= winLo);

        float sc1[8], sc2[8];
        float tS = -1e30f, tW = -1e30f;
        #pragma unroll
        for (int hh = 0; hh < 8; ++hh) {
            float2 f1 = unpack2(s1[hh]);
            float2 f2 = unpack2(s2[hh]);
            sc1[hh] = (f1.x + f1.y) * SCALE;
            sc2[hh] = (f2.x + f2.y) * SCALE;
            if (c1) { tS = fmaxf(tS, sc1[hh]); if (w1) tW = fmaxf(tW, sc1[hh]); }
            if (c2) { tS = fmaxf(tS, sc2[hh]); if (w2) tW = fmaxf(tW, sc2[hh]); }
        }
        #pragma unroll
        for (int off = 16; off; off >>= 1) {
            tS = fmaxf(tS, __shfl_xor_sync(~0u, tS, off));
            tW = fmaxf(tW, __shfl_xor_sync(~0u, tW, off));
        }

        const bool doS = selAct;
        const bool doW = swaAct && (tW > -1e29f);
        float t = -1e30f;
        if (doS) t = tS;
        if (doW) t = fmaxf(t, tW);
        if (t > mU) {
            float f = __expf(mU - t);
            u64t f2p = pack2(f, f);
            #pragma unroll
            for (int i = 0; i < 8; ++i) {
                mul2(accS2[i], accS2[i], f2p);
                mul2(accW2[i], accW2[i], f2p);
                mul2(lsw2[i], lsw2[i], f2p);
            }
            mU = t;
        }

        // exps + transposed prob store + packed masked sums
        float e1[8], e2[8];
        #pragma unroll
        for (int hh = 0; hh < 8; ++hh) {
            e1[hh] = __expf(sc1[hh] - mU);
            e2[hh] = __expf(sc2[hh] - mU);
        }
        {
            float4* pw = (float4*)probsW;
            if (c1) {
                pw[lane * 2]     = make_float4(e1[0], e1[1], e1[2], e1[3]);
                pw[lane * 2 + 1] = make_float4(e1[4], e1[5], e1[6], e1[7]);
            }
            if (c2) {
                pw[(lane + 32) * 2]     = make_float4(e2[0], e2[1], e2[2], e2[3]);
                pw[(lane + 32) * 2 + 1] = make_float4(e2[4], e2[5], e2[6], e2[7]);
            }
        }
        u64t sum2[8];
        #pragma unroll
        for (int hh = 0; hh < 8; ++hh) {
            float sS = (doS && c1 ? e1[hh] : 0.f) + (doS && c2 ? e2[hh] : 0.f);
            float sW = (w1 ? e1[hh] : 0.f) + (w2 ? e2[hh] : 0.f);
            sum2[hh] = pack2(sS, sW);
        }
        #pragma unroll
        for (int off = 16; off; off >>= 1) {
            #pragma unroll
            for (int hh = 0; hh < 8; ++hh) {
                u64t o = __shfl_xor_sync(~0u, sum2[hh], off);
                add2(sum2[hh], sum2[hh], o);
            }
        }
        #pragma unroll
        for (int hh = 0; hh < 8; ++hh) add2(lsw2[hh], lsw2[hh], sum2[hh]);
        __syncwarp();

        // ---- PV pass: lane owns 2 dims x 8 heads; P uniform, V minimal ----
        const u64t* vB = (const u64t*)Vt + lane;     // Vt[j*68 + 2*lane] => u64 idx j*34+lane
        const float4* pB = (const float4*)probsW;
        const int jlo = max(0, winLo - base);

        if (doS && doW) {
            for (int j = 0; j < jlo; ++j) {
                u64t vj = vB[j * 34];
                float4 pa = pB[j * 2], pb = pB[j * 2 + 1];
                ffma2(accS2[0], pack2(pa.x, pa.x), vj);
                ffma2(accS2[1], pack2(pa.y, pa.y), vj);
                ffma2(accS2[2], pack2(pa.z, pa.z), vj);
                ffma2(accS2[3], pack2(pa.w, pa.w), vj);
                ffma2(accS2[4], pack2(pb.x, pb.x), vj);
                ffma2(accS2[5], pack2(pb.y, pb.y), vj);
                ffma2(accS2[6], pack2(pb.z, pb.z), vj);
                ffma2(accS2[7], pack2(pb.w, pb.w), vj);
            }
            u64t accT2[8];
            #pragma unroll
            for (int i = 0; i < 8; ++i) accT2[i] = 0ull;
            for (int j = jlo; j <= jhi; ++j) {
                u64t vj = vB[j * 34];
                float4 pa = pB[j * 2], pb = pB[j * 2 + 1];
                ffma2(accT2[0], pack2(pa.x, pa.x), vj);
                ffma2(accT2[1], pack2(pa.y, pa.y), vj);
                ffma2(accT2[2], pack2(pa.z, pa.z), vj);
                ffma2(accT2[3], pack2(pa.w, pa.w), vj);
                ffma2(accT2[4], pack2(pb.x, pb.x), vj);
                ffma2(accT2[5], pack2(pb.y, pb.y), vj);
                ffma2(accT2[6], pack2(pb.z, pb.z), vj);
                ffma2(accT2[7], pack2(pb.w, pb.w), vj);
            }
            #pragma unroll
            for (int i = 0; i < 8; ++i) {
                add2(accS2[i], accS2[i], accT2[i]);
                add2(accW2[i], accW2[i], accT2[i]);
            }
        } else if (doS) {
            for (int j = 0; j <= jhi; ++j) {
                u64t vj = vB[j * 34];
                float4 pa = pB[j * 2], pb = pB[j * 2 + 1];
                ffma2(accS2[0], pack2(pa.x, pa.x), vj);
                ffma2(accS2[1], pack2(pa.y, pa.y), vj);
                ffma2(accS2[2], pack2(pa.z, pa.z), vj);
                ffma2(accS2[3], pack2(pa.w, pa.w), vj);
                ffma2(accS2[4], pack2(pb.x, pb.x), vj);
                ffma2(accS2[5], pack2(pb.y, pb.y), vj);
                ffma2(accS2[6], pack2(pb.z, pb.z), vj);
                ffma2(accS2[7], pack2(pb.w, pb.w), vj);
            }
        } else if (doW) {
            for (int j = jlo; j <= jhi; ++j) {
                u64t vj = vB[j * 34];
                float4 pa = pB[j * 2], pb = pB[j * 2 + 1];
                ffma2(accW2[0], pack2(pa.x, pa.x), vj);
                ffma2(accW2[1], pack2(pa.y, pa.y), vj);
                ffma2(accW2[2], pack2(pa.z, pa.z), vj);
                ffma2(accW2[3], pack2(pa.w, pa.w), vj);
                ffma2(accW2[4], pack2(pb.x, pb.x), vj);
                ffma2(accW2[5], pack2(pb.y, pb.y), vj);
                ffma2(accW2[6], pack2(pb.z, pb.z), vj);
                ffma2(accW2[7], pack2(pb.w, pb.w), vj);
            }
        }
    }

    // ---- combine per head and store (lane owns dims 2*lane, 2*lane+1) ----
    #pragma unroll
    for (int hh = 0; hh < 8; ++hh) {
        float g0 = __shfl_sync(~0u, gate0, hh * 4);
        float g1 = __shfl_sync(~0u, gate1, hh * 4);
        float2 lw = unpack2(lsw2[hh]);
        float invS = g0 / fmaxf(lw.x, 1e-20f);
        float invW = g1 / fmaxf(lw.y, 1e-20f);
        float2 aS = unpack2(accS2[hh]);
        float2 aW = unpack2(accW2[hh]);
        float2* op = (float2*)(out + (s * HQ + hkv * GQA + hh) * DIM + 2 * lane);
        float2 cur = *op;
        cur.x += invS * aS.x + invW * aW.x;
        cur.y += invS * aS.y + invW * aW.y;
        *op = cur;
    }
}

// ---------------------------------------------------------------------------
extern "C" void kernel_launch(void* const* d_in, const int* in_sizes, int n_in,
                              void* d_out, int out_size)
{
    const float* q  = (const float*)d_in[0];
    const float* k  = (const float*)d_in[1];
    const float* v  = (const float*)d_in[2];
    const float* wk = (const float*)d_in[3];
    const float* wv = (const float*)d_in[4];
    const float* wg = (const float*)d_in[5];
    float* out = (float*)d_out;

    compress_kernel<<<256, NT>>>(k, v, wk, wv);
    cmp_kernel<<<(S_LEN / QT) * HKV, NT>>>(q, wg, out);

    const size_t smem_bytes = (17408 + 4352 + QT * 512) * sizeof(float);  // 103424 B
    cudaFuncSetAttribute(branch_kernel,
                         cudaFuncAttributeMaxDynamicSharedMemorySize, (int)smem_bytes);
    branch_kernel<<<(S_LEN / QT) * HKV, NT, smem_bytes>>>(q, k, v, wg, out);
}

// round 9
// speedup vs baseline: 3.1031x; 1.0768x over previous
#include <cuda_runtime.h>
#include <cstdint>

#define S_LEN  2048
#define HKV    2
#define HQ     16
#define GQA    8
#define DIM    64
#define LC     32
#define CSTRIDE 16
#define LB     64
#define KSEL   8
#define WIN    512
#define SC_N   127
#define NOUT   31
#define SCALE  0.125f
#define QT     8
#define NT     256
#define RS     76            // padded row stride (floats) for K/V tiles: conflict-free LDS.128
#define RS2    19            // RS in ulonglong2
#define RSU    38            // RS in u64

typedef unsigned long long u64t;

__device__ float g_ck[HKV * SC_N * DIM];
__device__ float g_cv[HKV * SC_N * DIM];
__device__ unsigned g_selmask[HKV * S_LEN];

__device__ __forceinline__ float dot4(float4 a, float4 b) {
    return a.x * b.x + a.y * b.y + a.z * b.z + a.w * b.w;
}
__device__ __forceinline__ void ffma2(u64t& d, u64t a, u64t b) {
    asm("fma.rn.f32x2 %0, %1, %2, %0;" : "+l"(d) : "l"(a), "l"(b));
}
__device__ __forceinline__ void mul2(u64t& d, u64t a, u64t b) {
    asm("mul.rn.f32x2 %0, %1, %2;" : "=l"(d) : "l"(a), "l"(b));
}
__device__ __forceinline__ void add2(u64t& d, u64t a, u64t b) {
    asm("add.rn.f32x2 %0, %1, %2;" : "=l"(d) : "l"(a), "l"(b));
}
__device__ __forceinline__ u64t pack2(float lo, float hi) {
    u64t r; asm("mov.b64 %0, {%1, %2};" : "=l"(r) : "f"(lo), "f"(hi)); return r;
}
__device__ __forceinline__ float2 unpack2(u64t a) {
    float2 r; asm("mov.b64 {%0, %1}, %2;" : "=f"(r.x), "=f"(r.y) : "l"(a)); return r;
}
__device__ __forceinline__ void cp16(void* sdst, const void* gsrc) {
    uint32_t sa = (uint32_t)__cvta_generic_to_shared(sdst);
    asm volatile("cp.async.cg.shared.global [%0], [%1], 16;" :: "r"(sa), "l"(gsrc));
}
#define CP_COMMIT() asm volatile("cp.async.commit_group;")
#define CP_WAIT0()  asm volatile("cp.async.wait_group 0;")

extern __shared__ float pool3[];

// ---------------------------------------------------------------------------
// conv1d compressor: block = (hkv, k/v, o-quarter, 8 compressed positions)
// ---------------------------------------------------------------------------
__global__ void __launch_bounds__(256) compress_kernel(
    const float* __restrict__ k, const float* __restrict__ v,
    const float* __restrict__ wk, const float* __restrict__ wv)
{
    const int b     = blockIdx.x;        // 256 blocks
    const int hkv   = b & 1;
    const int isV   = (b >> 1) & 1;
    const int oq    = (b >> 2) & 3;
    const int c0    = (b >> 4) * 8;
    const float* src = isV ? v : k;
    const float* w   = isV ? wv : wk;
    float* dst = isV ? g_cv : g_ck;

    __shared__ float xs[144 * 64];
    __shared__ float red[16 * 8 * 16];
    const int tid = threadIdx.x;

    for (int idx = tid; idx < 144 * 16; idx += NT) {
        int row = idx >> 4, quad = idx & 15;
        int pos = c0 * CSTRIDE + row;
        float4 val = make_float4(0.f, 0.f, 0.f, 0.f);
        if (pos < S_LEN)
            val = __ldg((const float4*)(src + (pos * HKV + hkv) * DIM) + quad);
        ((float4*)(xs + row * 64))[quad] = val;
    }
    __syncthreads();

    const int ol   = tid & 15;
    const int o    = oq * 16 + ol;
    const int part = tid >> 4;
    float acc[8];
    #pragma unroll
    for (int cc = 0; cc < 8; ++cc) acc[cc] = 0.f;

    for (int i = part * 4; i < part * 4 + 4; ++i) {
        const float4* w4 = (const float4*)(w + (o * DIM + i) * LC);
        #pragma unroll
        for (int t4 = 0; t4 < 8; ++t4) {
            float4 a = __ldg(&w4[t4]);
            int t = t4 * 4;
            #pragma unroll
            for (int cc = 0; cc < 8; ++cc) {
                const float* xr = xs + (cc * 16 + t) * 64 + i;
                acc[cc] += a.x * xr[0] + a.y * xr[64] + a.z * xr[128] + a.w * xr[192];
            }
        }
    }
    #pragma unroll
    for (int cc = 0; cc < 8; ++cc) red[(part * 8 + cc) * 16 + ol] = acc[cc];
    __syncthreads();
    if (part == 0) {
        #pragma unroll
        for (int cc = 0; cc < 8; ++cc) {
            if (c0 + cc < SC_N) {
                float a = 0.f;
                #pragma unroll
                for (int p = 0; p < 16; ++p) a += red[(p * 8 + cc) * 16 + ol];
                dst[(hkv * SC_N + c0 + cc) * DIM + o] = a;
            }
        }
    }
}

// ---------------------------------------------------------------------------
// Kernel 2: compressed attention + block selection (R8-style restructure).
// smem: ckT [128][76] @0 (probsT overlays after scores), cvT [128][76] @9728,
//       qs [QT][8][68] @19456, pkv [QT][128] @23808.  Total 24832 f = 99328 B
// ---------------------------------------------------------------------------
__global__ void __launch_bounds__(256) cmp_kernel(
    const float* __restrict__ q, const float* __restrict__ wg,
    float* __restrict__ out)
{
    float* ckT  = pool3;
    float* cvT  = pool3 + 9728;
    float* qs   = pool3 + 19456;
    float* pkv  = pool3 + 23808;

    const int bx   = blockIdx.x;
    const int hkv  = bx & 1;
    const int s0   = (bx >> 1) * QT;
    const int tid  = threadIdx.x;
    const int lane = tid & 31;
    const int warp = tid >> 5;
    const int s    = s0 + warp;

    // stage ck/cv tiles (row 127 duplicates 126; always masked)
    {
        const float* ckb = g_ck + hkv * SC_N * DIM;
        const float* cvb = g_cv + hkv * SC_N * DIM;
        for (int idx = tid; idx < 128 * 16; idx += NT) {
            int row = idx >> 4, quad = idx & 15;
            int c = row < SC_N ? row : SC_N - 1;
            cp16(ckT + row * RS + quad * 4, ckb + c * DIM + quad * 4);
            cp16(cvT + row * RS + quad * 4, cvb + c * DIM + quad * 4);
        }
        CP_COMMIT();
    }

    // gates (old mapping h=lane>>2) + stage q
    float g2;
    {
        const int h   = lane >> 2;
        const int d16 = lane & 3;
        const float4* qrow = (const float4*)(q + (s * HQ + hkv * GQA + h) * DIM);
        float4 qf[4];
        #pragma unroll
        for (int r = 0; r < 4; ++r) qf[r] = __ldg(&qrow[d16 * 4 + r]);
        const float4* wrow = (const float4*)(wg + 2 * DIM);
        float a = 0.f;
        #pragma unroll
        for (int r = 0; r < 4; ++r) a += dot4(qf[r], __ldg(&wrow[d16 * 4 + r]));
        a += __shfl_xor_sync(~0u, a, 1);
        a += __shfl_xor_sync(~0u, a, 2);
        g2 = a;
        float4* qdst = (float4*)(qs + warp * 544 + h * 68);
        #pragma unroll
        for (int r = 0; r < 4; ++r) qdst[d16 * 4 + r] = qf[r];
    }

    const int Nc = (s >= 31) ? (((s - 31) >> 4) + 1) : 0;
    const ulonglong2* qq2 = (const ulonglong2*)(qs + warp * 544);

    CP_WAIT0();
    __syncthreads();

    // ---- score pass: 2 sub-tiles, lane owns keys {t*64+lane, t*64+lane+32} ----
    float scA[4][8];
    #pragma unroll
    for (int t = 0; t < 2; ++t) {
        u64t s1[8], s2[8];
        #pragma unroll
        for (int hh = 0; hh < 8; ++hh) { s1[hh] = 0ull; s2[hh] = 0ull; }
        const ulonglong2* kA = (const ulonglong2*)ckT + (t * 64 + lane) * RS2;
        const ulonglong2* kB = kA + 32 * RS2;
        #pragma unroll
        for (int d4 = 0; d4 < 16; ++d4) {
            ulonglong2 a = kA[d4];
            ulonglong2 bb = kB[d4];
            #pragma unroll
            for (int hh = 0; hh < 8; ++hh) {
                ulonglong2 qv = qq2[hh * 17 + d4];
                ffma2(s1[hh], qv.x, a.x);
                ffma2(s1[hh], qv.y, a.y);
                ffma2(s2[hh], qv.x, bb.x);
                ffma2(s2[hh], qv.y, bb.y);
            }
        }
        #pragma unroll
        for (int hh = 0; hh < 8; ++hh) {
            float2 f1 = unpack2(s1[hh]);
            float2 f2 = unpack2(s2[hh]);
            scA[2 * t][hh]     = (f1.x + f1.y) * SCALE;
            scA[2 * t + 1][hh] = (f2.x + f2.y) * SCALE;
        }
    }
    __syncthreads();    // all warps done reading ckT; probsT may overlay it

    float* probsW = pool3 + warp * 1024;   // [128][8] overlay on ckT
    float* pkvW   = pkv + warp * 128;

    // key validity: key ki -> c = ki*32 + lane
    bool valid[4];
    #pragma unroll
    for (int ki = 0; ki < 4; ++ki) valid[ki] = (ki * 32 + lane) < Nc;

    // per-head exact max
    float m[8];
    #pragma unroll
    for (int hh = 0; hh < 8; ++hh) {
        float lm = -1e30f;
        #pragma unroll
        for (int ki = 0; ki < 4; ++ki)
            if (valid[ki]) lm = fmaxf(lm, scA[ki][hh]);
        #pragma unroll
        for (int off = 16; off; off >>= 1)
            lm = fmaxf(lm, __shfl_xor_sync(~0u, lm, off));
        m[hh] = lm;
    }

    // exact exps + per-head sums (packed butterflies)
    float e[4][8];
    #pragma unroll
    for (int hh = 0; hh < 8; ++hh)
        #pragma unroll
        for (int ki = 0; ki < 4; ++ki)
            e[ki][hh] = valid[ki] ? expf(scA[ki][hh] - m[hh]) : 0.f;

    float inv[8];
    #pragma unroll
    for (int hp = 0; hp < 4; ++hp) {
        float sa = e[0][2*hp]   + e[1][2*hp]   + e[2][2*hp]   + e[3][2*hp];
        float sb = e[0][2*hp+1] + e[1][2*hp+1] + e[2][2*hp+1] + e[3][2*hp+1];
        u64t p = pack2(sa, sb);
        #pragma unroll
        for (int off = 16; off; off >>= 1) {
            u64t o = __shfl_xor_sync(~0u, p, off);
            add2(p, p, o);
        }
        float2 f = unpack2(p);
        inv[2*hp]   = (f.x > 0.f) ? (1.f / f.x) : 0.f;
        inv[2*hp+1] = (f.y > 0.f) ? (1.f / f.y) : 0.f;
    }

    // normalized probs -> probsW [c][8]; pkv
    #pragma unroll
    for (int ki = 0; ki < 4; ++ki) {
        int c = ki * 32 + lane;
        float p0 = e[ki][0]*inv[0], p1 = e[ki][1]*inv[1];
        float p2 = e[ki][2]*inv[2], p3 = e[ki][3]*inv[3];
        float p4 = e[ki][4]*inv[4], p5 = e[ki][5]*inv[5];
        float p6 = e[ki][6]*inv[6], p7 = e[ki][7]*inv[7];
        float4* pw = (float4*)(probsW + c * 8);
        pw[0] = make_float4(p0, p1, p2, p3);
        pw[1] = make_float4(p4, p5, p6, p7);
        pkvW[c] = p0 + p1 + p2 + p3 + p4 + p5 + p6 + p7;
    }
    __syncwarp();

    // pooling + top-8 (lax.top_k tie-break: value desc, index asc)
    {
        float myval;
        if (lane < NOUT) {
            const float* pv = pkvW + lane * 4;
            myval = (pv[0] + pv[1] + pv[2] + pv[3] + pv[4]) / 5.0f;
        } else {
            myval = -1.0f;
        }
        if (lane == (s >> 6)) myval = __int_as_float(0x7f800000);
        unsigned mask = 0;
        #pragma unroll
        for (int r = 0; r < KSEL; ++r) {
            float bv = myval; int bi = lane;
            #pragma unroll
            for (int off = 16; off; off >>= 1) {
                float ov = __shfl_xor_sync(~0u, bv, off);
                int   oi = __shfl_xor_sync(~0u, bi, off);
                if (ov > bv || (ov == bv && oi < bi)) { bv = ov; bi = oi; }
            }
            mask |= 1u << bi;
            if (lane == bi) myval = __int_as_float(0xff800000);
        }
        if (lane == 0) g_selmask[hkv * S_LEN + s] = mask;
    }

    // ---- PV: lane owns dims (2*lane, 2*lane+1) x 8 heads ----
    u64t acc2[8];
    #pragma unroll
    for (int i = 0; i < 8; ++i) acc2[i] = 0ull;
    {
        const u64t* vB = (const u64t*)cvT + lane;
        const float4* pB = (const float4*)probsW;
        #pragma unroll 2
        for (int c = 0; c < Nc; ++c) {
            u64t vj = vB[c * RSU];
            float4 pa = pB[c * 2], pb = pB[c * 2 + 1];
            ffma2(acc2[0], pack2(pa.x, pa.x), vj);
            ffma2(acc2[1], pack2(pa.y, pa.y), vj);
            ffma2(acc2[2], pack2(pa.z, pa.z), vj);
            ffma2(acc2[3], pack2(pa.w, pa.w), vj);
            ffma2(acc2[4], pack2(pb.x, pb.x), vj);
            ffma2(acc2[5], pack2(pb.y, pb.y), vj);
            ffma2(acc2[6], pack2(pb.z, pb.z), vj);
            ffma2(acc2[7], pack2(pb.w, pb.w), vj);
        }
    }
    #pragma unroll
    for (int hh = 0; hh < 8; ++hh) {
        float g2h = __shfl_sync(~0u, g2, hh * 4);
        float2 a = unpack2(acc2[hh]);
        float2* op = (float2*)(out + (s * HQ + hkv * GQA + hh) * DIM + 2 * lane);
        *op = make_float2(g2h * a.x, g2h * a.y);
    }
}

// ---------------------------------------------------------------------------
// Kernel 3: sel + swa (R8 structure, RS=76 conflict-free K rows).
// smem: stage0 K|V [9728], stage1 K|V [9728], qs @19456 [4352], probsT @23808 [4096]
// ---------------------------------------------------------------------------
__device__ __forceinline__ void stage_issue(
    const float* __restrict__ k, const float* __restrict__ v,
    int hkv, int base, float* buf, int tid)
{
    float* Kd = buf;
    float* Vd = buf + 4864;
    #pragma unroll
    for (int r = 0; r < 4; ++r) {
        int idx = tid + r * NT;
        int row = idx >> 4, quad = idx & 15;
        int pos = base + row;
        cp16(Kd + row * RS + quad * 4, (const float4*)(k + (pos * HKV + hkv) * DIM) + quad);
        cp16(Vd + row * RS + quad * 4, (const float4*)(v + (pos * HKV + hkv) * DIM) + quad);
    }
}

__global__ void __launch_bounds__(256) branch_kernel(
    const float* __restrict__ q, const float* __restrict__ k,
    const float* __restrict__ v, const float* __restrict__ wg,
    float* __restrict__ out)
{
    __shared__ unsigned selmaskSh[QT];
    __shared__ int blkList[32];
    __shared__ int nblkSh;

    float* qs     = pool3 + 19456;   // [QT][8][68]
    float* probsT = pool3 + 23808;   // [QT][64][8]

    const int bx   = blockIdx.x;
    const int hkv  = bx & 1;
    const int s0   = (bx >> 1) * QT;
    const int tid  = threadIdx.x;
    const int lane = tid & 31;
    const int warp = tid >> 5;
    const int s    = s0 + warp;

    float gate0, gate1;
    {
        const int h   = lane >> 2;
        const int d16 = lane & 3;
        const float4* qrow = (const float4*)(q + (s * HQ + hkv * GQA + h) * DIM);
        float4 qf[4];
        #pragma unroll
        for (int r = 0; r < 4; ++r) qf[r] = __ldg(&qrow[d16 * 4 + r]);
        #pragma unroll
        for (int e = 0; e < 2; ++e) {
            const float4* wrow = (const float4*)(wg + e * DIM);
            float a = 0.f;
            #pragma unroll
            for (int r = 0; r < 4; ++r) a += dot4(qf[r], __ldg(&wrow[d16 * 4 + r]));
            a += __shfl_xor_sync(~0u, a, 1);
            a += __shfl_xor_sync(~0u, a, 2);
            if (e == 0) gate0 = a; else gate1 = a;
        }
        float4* qdst = (float4*)(qs + warp * 544 + h * 68);
        #pragma unroll
        for (int r = 0; r < 4; ++r) qdst[d16 * 4 + r] = qf[r];
    }

    if (lane == 0) selmaskSh[warp] = g_selmask[hkv * S_LEN + s];
    __syncthreads();
    if (tid == 0) {
        unsigned cmb = 0;
        #pragma unroll
        for (int qq = 0; qq < QT; ++qq) cmb |= selmaskSh[qq];
        int loS = s0 - (WIN - 1); if (loS < 0) loS = 0;
        int lowBlk = loS >> 6;
        int hiBlk  = (s0 + QT - 1) >> 6;
        unsigned wmask = (hiBlk >= 31 ? 0xFFFFFFFFu : ((1u << (hiBlk + 1)) - 1u))
                       & ~((1u << lowBlk) - 1u);
        unsigned m = cmb | wmask;
        int n = 0;
        while (m) { int bb = __ffs(m) - 1; m &= m - 1; blkList[n++] = bb; }
        nblkSh = n;
    }
    __syncthreads();

    const unsigned selMine = selmaskSh[warp];
    const int nblk = nblkSh;

    u64t accS2[8], accW2[8], lsw2[8];
    #pragma unroll
    for (int i = 0; i < 8; ++i) { accS2[i] = 0ull; accW2[i] = 0ull; lsw2[i] = 0ull; }
    float mU = -1e30f;
    const int winLo = s - (WIN - 1);
    float* probsW = probsT + warp * 512;
    const ulonglong2* qq2 = (const ulonglong2*)(qs + warp * 544);

    stage_issue(k, v, hkv, blkList[0] * LB, pool3, tid);
    CP_COMMIT();

    for (int it = 0; it < nblk; ++it) {
        CP_WAIT0();
        __syncthreads();
        if (it + 1 < nblk) {
            stage_issue(k, v, hkv, blkList[it + 1] * LB, pool3 + ((it + 1) & 1) * 9728, tid);
            CP_COMMIT();
        }
        const float* Kt = pool3 + (it & 1) * 9728;
        const float* Vt = Kt + 4864;
        const int b = blkList[it];
        const int base = b * LB;

        if (base > s) continue;
        const bool selAct = (selMine >> b) & 1u;
        const bool swaAct = (base + 63) >= winLo;
        if (!(selAct || swaAct)) continue;

        // ---- score pass ----
        u64t s1[8], s2[8];
        #pragma unroll
        for (int hh = 0; hh < 8; ++hh) { s1[hh] = 0ull; s2[hh] = 0ull; }
        {
            const ulonglong2* kA = (const ulonglong2*)Kt + lane * RS2;
            const ulonglong2* kB = kA + 32 * RS2;
            #pragma unroll
            for (int d4 = 0; d4 < 16; ++d4) {
                ulonglong2 a = kA[d4];
                ulonglong2 bb = kB[d4];
                #pragma unroll
                for (int hh = 0; hh < 8; ++hh) {
                    ulonglong2 qv = qq2[hh * 17 + d4];
                    ffma2(s1[hh], qv.x, a.x);
                    ffma2(s1[hh], qv.y, a.y);
                    ffma2(s2[hh], qv.x, bb.x);
                    ffma2(s2[hh], qv.y, bb.y);
                }
            }
        }

        const int jhi  = min(63, s - base);
        const int pos1 = base + lane;
        const bool c1 = (lane <= jhi);
        const bool c2 = (lane + 32 <= jhi);
        const bool w1 = c1 && (pos1 >= winLo);
        const bool w2 = c2 && (pos1 + 32 >= winLo);

        float sc1[8], sc2[8];
        float tS = -1e30f, tW = -1e30f;
        #pragma unroll
        for (int hh = 0; hh < 8; ++hh) {
            float2 f1 = unpack2(s1[hh]);
            float2 f2 = unpack2(s2[hh]);
            sc1[hh] = (f1.x + f1.y) * SCALE;
            sc2[hh] = (f2.x + f2.y) * SCALE;
            if (c1) { tS = fmaxf(tS, sc1[hh]); if (w1) tW = fmaxf(tW, sc1[hh]); }
            if (c2) { tS = fmaxf(tS, sc2[hh]); if (w2) tW = fmaxf(tW, sc2[hh]); }
        }
        #pragma unroll
        for (int off = 16; off; off >>= 1) {
            tS = fmaxf(tS, __shfl_xor_sync(~0u, tS, off));
            tW = fmaxf(tW, __shfl_xor_sync(~0u, tW, off));
        }

        const bool doS = selAct;
        const bool doW = swaAct && (tW > -1e29f);
        float t = -1e30f;
        if (doS) t = tS;
        if (doW) t = fmaxf(t, tW);
        if (t > mU) {
            float f = __expf(mU - t);
            u64t f2p = pack2(f, f);
            #pragma unroll
            for (int i = 0; i < 8; ++i) {
                mul2(accS2[i], accS2[i], f2p);
                mul2(accW2[i], accW2[i], f2p);
                mul2(lsw2[i], lsw2[i], f2p);
            }
            mU = t;
        }

        float e1[8], e2[8];
        #pragma unroll
        for (int hh = 0; hh < 8; ++hh) {
            e1[hh] = __expf(sc1[hh] - mU);
            e2[hh] = __expf(sc2[hh] - mU);
        }
        {
            float4* pw = (float4*)probsW;
            if (c1) {
                pw[lane * 2]     = make_float4(e1[0], e1[1], e1[2], e1[3]);
                pw[lane * 2 + 1] = make_float4(e1[4], e1[5], e1[6], e1[7]);
            }
            if (c2) {
                pw[(lane + 32) * 2]     = make_float4(e2[0], e2[1], e2[2], e2[3]);
                pw[(lane + 32) * 2 + 1] = make_float4(e2[4], e2[5], e2[6], e2[7]);
            }
        }
        u64t sum2[8];
        #pragma unroll
        for (int hh = 0; hh < 8; ++hh) {
            float sS = (doS && c1 ? e1[hh] : 0.f) + (doS && c2 ? e2[hh] : 0.f);
            float sW = (w1 ? e1[hh] : 0.f) + (w2 ? e2[hh] : 0.f);
            sum2[hh] = pack2(sS, sW);
        }
        #pragma unroll
        for (int off = 16; off; off >>= 1) {
            #pragma unroll
            for (int hh = 0; hh < 8; ++hh) {
                u64t o = __shfl_xor_sync(~0u, sum2[hh], off);
                add2(sum2[hh], sum2[hh], o);
            }
        }
        #pragma unroll
        for (int hh = 0; hh < 8; ++hh) add2(lsw2[hh], lsw2[hh], sum2[hh]);
        __syncwarp();

        // ---- PV pass ----
        const u64t* vB = (const u64t*)Vt + lane;
        const float4* pB = (const float4*)probsW;
        const int jlo = max(0, winLo - base);

        if (doS && doW) {
            for (int j = 0; j < jlo; ++j) {
                u64t vj = vB[j * RSU];
                float4 pa = pB[j * 2], pb = pB[j * 2 + 1];
                ffma2(accS2[0], pack2(pa.x, pa.x), vj);
                ffma2(accS2[1], pack2(pa.y, pa.y), vj);
                ffma2(accS2[2], pack2(pa.z, pa.z), vj);
                ffma2(accS2[3], pack2(pa.w, pa.w), vj);
                ffma2(accS2[4], pack2(pb.x, pb.x), vj);
                ffma2(accS2[5], pack2(pb.y, pb.y), vj);
                ffma2(accS2[6], pack2(pb.z, pb.z), vj);
                ffma2(accS2[7], pack2(pb.w, pb.w), vj);
            }
            u64t accT2[8];
            #pragma unroll
            for (int i = 0; i < 8; ++i) accT2[i] = 0ull;
            for (int j = jlo; j <= jhi; ++j) {
                u64t vj = vB[j * RSU];
                float4 pa = pB[j * 2], pb = pB[j * 2 + 1];
                ffma2(accT2[0], pack2(pa.x, pa.x), vj);
                ffma2(accT2[1], pack2(pa.y, pa.y), vj);
                ffma2(accT2[2], pack2(pa.z, pa.z), vj);
                ffma2(accT2[3], pack2(pa.w, pa.w), vj);
                ffma2(accT2[4], pack2(pb.x, pb.x), vj);
                ffma2(accT2[5], pack2(pb.y, pb.y), vj);
                ffma2(accT2[6], pack2(pb.z, pb.z), vj);
                ffma2(accT2[7], pack2(pb.w, pb.w), vj);
            }
            #pragma unroll
            for (int i = 0; i < 8; ++i) {
                add2(accS2[i], accS2[i], accT2[i]);
                add2(accW2[i], accW2[i], accT2[i]);
            }
        } else if (doS) {
            for (int j = 0; j <= jhi; ++j) {
                u64t vj = vB[j * RSU];
                float4 pa = pB[j * 2], pb = pB[j * 2 + 1];
                ffma2(accS2[0], pack2(pa.x, pa.x), vj);
                ffma2(accS2[1], pack2(pa.y, pa.y), vj);
                ffma2(accS2[2], pack2(pa.z, pa.z), vj);
                ffma2(accS2[3], pack2(pa.w, pa.w), vj);
                ffma2(accS2[4], pack2(pb.x, pb.x), vj);
                ffma2(accS2[5], pack2(pb.y, pb.y), vj);
                ffma2(accS2[6], pack2(pb.z, pb.z), vj);
                ffma2(accS2[7], pack2(pb.w, pb.w), vj);
            }
        } else if (doW) {
            for (int j = jlo; j <= jhi; ++j) {
                u64t vj = vB[j * RSU];
                float4 pa = pB[j * 2], pb = pB[j * 2 + 1];
                ffma2(accW2[0], pack2(pa.x, pa.x), vj);
                ffma2(accW2[1], pack2(pa.y, pa.y), vj);
                ffma2(accW2[2], pack2(pa.z, pa.z), vj);
                ffma2(accW2[3], pack2(pa.w, pa.w), vj);
                ffma2(accW2[4], pack2(pb.x, pb.x), vj);
                ffma2(accW2[5], pack2(pb.y, pb.y), vj);
                ffma2(accW2[6], pack2(pb.z, pb.z), vj);
                ffma2(accW2[7], pack2(pb.w, pb.w), vj);
            }
        }
    }

    // ---- combine per head and store ----
    #pragma unroll
    for (int hh = 0; hh < 8; ++hh) {
        float g0 = __shfl_sync(~0u, gate0, hh * 4);
        float g1 = __shfl_sync(~0u, gate1, hh * 4);
        float2 lw = unpack2(lsw2[hh]);
        float invS = g0 / fmaxf(lw.x, 1e-20f);
        float invW = g1 / fmaxf(lw.y, 1e-20f);
        float2 aS = unpack2(accS2[hh]);
        float2 aW = unpack2(accW2[hh]);
        float2* op = (float2*)(out + (s * HQ + hkv * GQA + hh) * DIM + 2 * lane);
        float2 cur = *op;
        cur.x += invS * aS.x + invW * aW.x;
        cur.y += invS * aS.y + invW * aW.y;
        *op = cur;
    }
}

// ---------------------------------------------------------------------------
extern "C" void kernel_launch(void* const* d_in, const int* in_sizes, int n_in,
                              void* d_out, int out_size)
{
    const float* q  = (const float*)d_in[0];
    const float* k  = (const float*)d_in[1];
    const float* v  = (const float*)d_in[2];
    const float* wk = (const float*)d_in[3];
    const float* wv = (const float*)d_in[4];
    const float* wg = (const float*)d_in[5];
    float* out = (float*)d_out;

    compress_kernel<<<256, NT>>>(k, v, wk, wv);

    const size_t smem_cmp = 24832 * sizeof(float);     // 99328 B
    cudaFuncSetAttribute(cmp_kernel,
                         cudaFuncAttributeMaxDynamicSharedMemorySize, (int)smem_cmp);
    cmp_kernel<<<(S_LEN / QT) * HKV, NT, smem_cmp>>>(q, wg, out);

    const size_t smem_br = 27904 * sizeof(float);      // 111616 B
    cudaFuncSetAttribute(branch_kernel,
                         cudaFuncAttributeMaxDynamicSharedMemorySize, (int)smem_br);
    branch_kernel<<<(S_LEN / QT) * HKV, NT, smem_br>>>(q, k, v, wg, out);
}

// round 10
// speedup vs baseline: 3.9014x; 1.2573x over previous
#include <cuda_runtime.h>
#include <cstdint>

#define S_LEN  2048
#define HKV    2
#define HQ     16
#define GQA    8
#define DIM    64
#define LC     32
#define CSTRIDE 16
#define LB     64
#define KSEL   8
#define WIN    512
#define SC_N   127
#define NOUT   31
#define SCALE  0.125f
#define QT     8
#define NT     256
#define RS     76            // padded row stride (floats): conflict-free LDS.128
#define RS2    19            // RS in ulonglong2
#define RSU    38            // RS in u64

typedef unsigned long long u64t;

__device__ float g_ck[HKV * SC_N * DIM];
__device__ float g_cv[HKV * SC_N * DIM];

__device__ __forceinline__ float dot4(float4 a, float4 b) {
    return a.x * b.x + a.y * b.y + a.z * b.z + a.w * b.w;
}
__device__ __forceinline__ void ffma2(u64t& d, u64t a, u64t b) {
    asm("fma.rn.f32x2 %0, %1, %2, %0;" : "+l"(d) : "l"(a), "l"(b));
}
__device__ __forceinline__ void mul2(u64t& d, u64t a, u64t b) {
    asm("mul.rn.f32x2 %0, %1, %2;" : "=l"(d) : "l"(a), "l"(b));
}
__device__ __forceinline__ void add2(u64t& d, u64t a, u64t b) {
    asm("add.rn.f32x2 %0, %1, %2;" : "=l"(d) : "l"(a), "l"(b));
}
__device__ __forceinline__ u64t pack2(float lo, float hi) {
    u64t r; asm("mov.b64 %0, {%1, %2};" : "=l"(r) : "f"(lo), "f"(hi)); return r;
}
__device__ __forceinline__ float2 unpack2(u64t a) {
    float2 r; asm("mov.b64 {%0, %1}, %2;" : "=f"(r.x), "=f"(r.y) : "l"(a)); return r;
}
__device__ __forceinline__ void cp16(void* sdst, const void* gsrc) {
    uint32_t sa = (uint32_t)__cvta_generic_to_shared(sdst);
    asm volatile("cp.async.cg.shared.global [%0], [%1], 16;" :: "r"(sa), "l"(gsrc));
}
#define CP_COMMIT() asm volatile("cp.async.commit_group;")
#define CP_WAIT0()  asm volatile("cp.async.wait_group 0;")

extern __shared__ float pool3[];

// ---------------------------------------------------------------------------
// conv1d compressor: block = (hkv, k/v, o-quarter, 8 compressed positions)
// ---------------------------------------------------------------------------
__global__ void __launch_bounds__(256) compress_kernel(
    const float* __restrict__ k, const float* __restrict__ v,
    const float* __restrict__ wk, const float* __restrict__ wv)
{
    const int b     = blockIdx.x;        // 256 blocks
    const int hkv   = b & 1;
    const int isV   = (b >> 1) & 1;
    const int oq    = (b >> 2) & 3;
    const int c0    = (b >> 4) * 8;
    const float* src = isV ? v : k;
    const float* w   = isV ? wv : wk;
    float* dst = isV ? g_cv : g_ck;

    __shared__ float xs[144 * 64];
    __shared__ float red[16 * 8 * 16];
    const int tid = threadIdx.x;

    for (int idx = tid; idx < 144 * 16; idx += NT) {
        int row = idx >> 4, quad = idx & 15;
        int pos = c0 * CSTRIDE + row;
        float4 val = make_float4(0.f, 0.f, 0.f, 0.f);
        if (pos < S_LEN)
            val = __ldg((const float4*)(src + (pos * HKV + hkv) * DIM) + quad);
        ((float4*)(xs + row * 64))[quad] = val;
    }
    __syncthreads();

    const int ol   = tid & 15;
    const int o    = oq * 16 + ol;
    const int part = tid >> 4;
    float acc[8];
    #pragma unroll
    for (int cc = 0; cc < 8; ++cc) acc[cc] = 0.f;

    for (int i = part * 4; i < part * 4 + 4; ++i) {
        const float4* w4 = (const float4*)(w + (o * DIM + i) * LC);
        #pragma unroll
        for (int t4 = 0; t4 < 8; ++t4) {
            float4 a = __ldg(&w4[t4]);
            int t = t4 * 4;
            #pragma unroll
            for (int cc = 0; cc < 8; ++cc) {
                const float* xr = xs + (cc * 16 + t) * 64 + i;
                acc[cc] += a.x * xr[0] + a.y * xr[64] + a.z * xr[128] + a.w * xr[192];
            }
        }
    }
    #pragma unroll
    for (int cc = 0; cc < 8; ++cc) red[(part * 8 + cc) * 16 + ol] = acc[cc];
    __syncthreads();
    if (part == 0) {
        #pragma unroll
        for (int cc = 0; cc < 8; ++cc) {
            if (c0 + cc < SC_N) {
                float a = 0.f;
                #pragma unroll
                for (int p = 0; p < 16; ++p) a += red[(p * 8 + cc) * 16 + ol];
                dst[(hkv * SC_N + c0 + cc) * DIM + o] = a;
            }
        }
    }
}

// ---------------------------------------------------------------------------
// Merged NSA kernel: phase 1 = cmp attention + top-8; phase 2 = sel + swa.
// smem (floats):
//   phase1: ckT [128][76] @0 (probs overlay after scores), cvT @9728,
//           qs @19456 [QT*544], pkv @23808 [QT*128]
//   phase2: stage0 K|V @0 [9728], stage1 @9728, qs @19456, probsT @23808 [QT*512]
// total 27904 f = 111616 B
// ---------------------------------------------------------------------------
__global__ void __launch_bounds__(256) nsa_main(
    const float* __restrict__ q, const float* __restrict__ k,
    const float* __restrict__ v, const float* __restrict__ wg,
    float* __restrict__ out)
{
    __shared__ unsigned selmaskSh[QT];
    __shared__ int blkList[32];
    __shared__ int nblkSh;

    float* ckT = pool3;
    float* cvT = pool3 + 9728;
    float* qs  = pool3 + 19456;
    float* pkv = pool3 + 23808;

    const int bxr  = gridDim.x - 1 - blockIdx.x;   // heavy-first
    const int hkv  = bxr & 1;
    const int s0   = (bxr >> 1) * QT;
    const int tid  = threadIdx.x;
    const int lane = tid & 31;
    const int warp = tid >> 5;
    const int s    = s0 + warp;

    // ---- stage ck/cv tiles (row >= SC_N clamped; always masked out) ----
    {
        const float* ckb = g_ck + hkv * SC_N * DIM;
        const float* cvb = g_cv + hkv * SC_N * DIM;
        for (int idx = tid; idx < 128 * 16; idx += NT) {
            int row = idx >> 4, quad = idx & 15;
            int c = row < SC_N ? row : SC_N - 1;
            cp16(ckT + row * RS + quad * 4, ckb + c * DIM + quad * 4);
            cp16(cvT + row * RS + quad * 4, cvb + c * DIM + quad * 4);
        }
        CP_COMMIT();
    }

    // ---- q fragments, all 3 gates, stage q ----
    float gate0, gate1, gate2;
    {
        const int h   = lane >> 2;
        const int d16 = lane & 3;
        const float4* qrow = (const float4*)(q + (s * HQ + hkv * GQA + h) * DIM);
        float4 qf[4];
        #pragma unroll
        for (int r = 0; r < 4; ++r) qf[r] = __ldg(&qrow[d16 * 4 + r]);
        #pragma unroll
        for (int e = 0; e < 3; ++e) {
            const float4* wrow = (const float4*)(wg + e * DIM);
            float a = 0.f;
            #pragma unroll
            for (int r = 0; r < 4; ++r) a += dot4(qf[r], __ldg(&wrow[d16 * 4 + r]));
            a += __shfl_xor_sync(~0u, a, 1);
            a += __shfl_xor_sync(~0u, a, 2);
            if (e == 0) gate0 = a; else if (e == 1) gate1 = a; else gate2 = a;
        }
        float4* qdst = (float4*)(qs + warp * 544 + h * 68);
        #pragma unroll
        for (int r = 0; r < 4; ++r) qdst[d16 * 4 + r] = qf[r];
    }

    const int Nc = (s >= 31) ? (((s - 31) >> 4) + 1) : 0;
    const ulonglong2* qq2 = (const ulonglong2*)(qs + warp * 544);

    CP_WAIT0();
    __syncthreads();

    // ======================= PHASE 1: compressed branch =====================
    // score pass: lane owns keys {t*64+lane, t*64+lane+32}, all 8 heads
    float scA[4][8];
    #pragma unroll
    for (int t = 0; t < 2; ++t) {
        u64t s1[8], s2[8];
        #pragma unroll
        for (int hh = 0; hh < 8; ++hh) { s1[hh] = 0ull; s2[hh] = 0ull; }
        const ulonglong2* kA = (const ulonglong2*)ckT + (t * 64 + lane) * RS2;
        const ulonglong2* kB = kA + 32 * RS2;
        #pragma unroll
        for (int d4 = 0; d4 < 16; ++d4) {
            ulonglong2 a = kA[d4];
            ulonglong2 bb = kB[d4];
            #pragma unroll
            for (int hh = 0; hh < 8; ++hh) {
                ulonglong2 qv = qq2[hh * 17 + d4];
                ffma2(s1[hh], qv.x, a.x);
                ffma2(s1[hh], qv.y, a.y);
                ffma2(s2[hh], qv.x, bb.x);
                ffma2(s2[hh], qv.y, bb.y);
            }
        }
        #pragma unroll
        for (int hh = 0; hh < 8; ++hh) {
            float2 f1 = unpack2(s1[hh]);
            float2 f2 = unpack2(s2[hh]);
            scA[2 * t][hh]     = (f1.x + f1.y) * SCALE;
            scA[2 * t + 1][hh] = (f2.x + f2.y) * SCALE;
        }
    }
    __syncthreads();    // ckT consumed; probs may overlay it

    {
        float* probsW = pool3 + warp * 1024;   // [128][8] overlay on ckT
        float* pkvW   = pkv + warp * 128;

        bool valid[4];
        #pragma unroll
        for (int ki = 0; ki < 4; ++ki) valid[ki] = (ki * 32 + lane) < Nc;

        float m[8];
        #pragma unroll
        for (int hh = 0; hh < 8; ++hh) {
            float lm = -1e30f;
            #pragma unroll
            for (int ki = 0; ki < 4; ++ki)
                if (valid[ki]) lm = fmaxf(lm, scA[ki][hh]);
            #pragma unroll
            for (int off = 16; off; off >>= 1)
                lm = fmaxf(lm, __shfl_xor_sync(~0u, lm, off));
            m[hh] = lm;
        }

        float e[4][8];
        #pragma unroll
        for (int hh = 0; hh < 8; ++hh)
            #pragma unroll
            for (int ki = 0; ki < 4; ++ki)
                e[ki][hh] = valid[ki] ? expf(scA[ki][hh] - m[hh]) : 0.f;

        float inv[8];
        #pragma unroll
        for (int hp = 0; hp < 4; ++hp) {
            float sa = e[0][2*hp]   + e[1][2*hp]   + e[2][2*hp]   + e[3][2*hp];
            float sb = e[0][2*hp+1] + e[1][2*hp+1] + e[2][2*hp+1] + e[3][2*hp+1];
            u64t p = pack2(sa, sb);
            #pragma unroll
            for (int off = 16; off; off >>= 1) {
                u64t o = __shfl_xor_sync(~0u, p, off);
                add2(p, p, o);
            }
            float2 f = unpack2(p);
            inv[2*hp]   = (f.x > 0.f) ? (1.f / f.x) : 0.f;
            inv[2*hp+1] = (f.y > 0.f) ? (1.f / f.y) : 0.f;
        }

        #pragma unroll
        for (int ki = 0; ki < 4; ++ki) {
            int c = ki * 32 + lane;
            float p0 = e[ki][0]*inv[0], p1 = e[ki][1]*inv[1];
            float p2 = e[ki][2]*inv[2], p3 = e[ki][3]*inv[3];
            float p4 = e[ki][4]*inv[4], p5 = e[ki][5]*inv[5];
            float p6 = e[ki][6]*inv[6], p7 = e[ki][7]*inv[7];
            float4* pw = (float4*)(probsW + c * 8);
            pw[0] = make_float4(p0, p1, p2, p3);
            pw[1] = make_float4(p4, p5, p6, p7);
            pkvW[c] = p0 + p1 + p2 + p3 + p4 + p5 + p6 + p7;
        }
        __syncwarp();

        // pooling + top-8 (lax.top_k tie-break: value desc, index asc)
        {
            float myval;
            if (lane < NOUT) {
                const float* pv = pkvW + lane * 4;
                myval = (pv[0] + pv[1] + pv[2] + pv[3] + pv[4]) / 5.0f;
            } else {
                myval = -1.0f;
            }
            if (lane == (s >> 6)) myval = __int_as_float(0x7f800000);
            unsigned mask = 0;
            #pragma unroll
            for (int r = 0; r < KSEL; ++r) {
                float bv = myval; int bi = lane;
                #pragma unroll
                for (int off = 16; off; off >>= 1) {
                    float ov = __shfl_xor_sync(~0u, bv, off);
                    int   oi = __shfl_xor_sync(~0u, bi, off);
                    if (ov > bv || (ov == bv && oi < bi)) { bv = ov; bi = oi; }
                }
                mask |= 1u << bi;
                if (lane == bi) myval = __int_as_float(0xff800000);
            }
            if (lane == 0) selmaskSh[warp] = mask;
        }

        // cmp PV -> out = g2 * cmp (plain store; phase 2 RMWs)
        u64t acc2[8];
        #pragma unroll
        for (int i = 0; i < 8; ++i) acc2[i] = 0ull;
        const u64t* vB = (const u64t*)cvT + lane;
        const float4* pB = (const float4*)probsW;
        #pragma unroll 2
        for (int c = 0; c < Nc; ++c) {
            u64t vj = vB[c * RSU];
            float4 pa = pB[c * 2], pb = pB[c * 2 + 1];
            ffma2(acc2[0], pack2(pa.x, pa.x), vj);
            ffma2(acc2[1], pack2(pa.y, pa.y), vj);
            ffma2(acc2[2], pack2(pa.z, pa.z), vj);
            ffma2(acc2[3], pack2(pa.w, pa.w), vj);
            ffma2(acc2[4], pack2(pb.x, pb.x), vj);
            ffma2(acc2[5], pack2(pb.y, pb.y), vj);
            ffma2(acc2[6], pack2(pb.z, pb.z), vj);
            ffma2(acc2[7], pack2(pb.w, pb.w), vj);
        }
        #pragma unroll
        for (int hh = 0; hh < 8; ++hh) {
            float g2h = __shfl_sync(~0u, gate2, hh * 4);
            float2 a = unpack2(acc2[hh]);
            float2* op = (float2*)(out + (s * HQ + hkv * GQA + hh) * DIM + 2 * lane);
            *op = make_float2(g2h * a.x, g2h * a.y);
        }
    }

    // ======================= PHASE 2: sel + swa ==============================
    __syncthreads();    // all warps done with ckT/cvT/probs; selmasks ready
    if (tid == 0) {
        unsigned cmb = 0;
        #pragma unroll
        for (int qq = 0; qq < QT; ++qq) cmb |= selmaskSh[qq];
        int loS = s0 - (WIN - 1); if (loS < 0) loS = 0;
        int lowBlk = loS >> 6;
        int hiBlk  = (s0 + QT - 1) >> 6;
        unsigned wmask = (hiBlk >= 31 ? 0xFFFFFFFFu : ((1u << (hiBlk + 1)) - 1u))
                       & ~((1u << lowBlk) - 1u);
        unsigned m = cmb | wmask;
        int n = 0;
        while (m) { int bb = __ffs(m) - 1; m &= m - 1; blkList[n++] = bb; }
        nblkSh = n;
    }
    __syncthreads();

    const unsigned selMine = selmaskSh[warp];
    const int nblk = nblkSh;

    u64t accS2[8], accW2[8], lsw2[8];
    #pragma unroll
    for (int i = 0; i < 8; ++i) { accS2[i] = 0ull; accW2[i] = 0ull; lsw2[i] = 0ull; }
    float mU = -1e30f;
    const int winLo = s - (WIN - 1);
    float* probsW2 = pool3 + 23808 + warp * 512;   // [64][8] per warp

    // prologue prefetch
    {
        int base = blkList[0] * LB;
        float* Kd = pool3;
        float* Vd = pool3 + 4864;
        #pragma unroll
        for (int r = 0; r < 4; ++r) {
            int idx = tid + r * NT;
            int row = idx >> 4, quad = idx & 15;
            int pos = base + row;
            cp16(Kd + row * RS + quad * 4, (const float4*)(k + (pos * HKV + hkv) * DIM) + quad);
            cp16(Vd + row * RS + quad * 4, (const float4*)(v + (pos * HKV + hkv) * DIM) + quad);
        }
        CP_COMMIT();
    }

    for (int it = 0; it < nblk; ++it) {
        CP_WAIT0();
        __syncthreads();
        if (it + 1 < nblk) {
            int base = blkList[it + 1] * LB;
            float* Kd = pool3 + ((it + 1) & 1) * 9728;
            float* Vd = Kd + 4864;
            #pragma unroll
            for (int r = 0; r < 4; ++r) {
                int idx = tid + r * NT;
                int row = idx >> 4, quad = idx & 15;
                int pos = base + row;
                cp16(Kd + row * RS + quad * 4, (const float4*)(k + (pos * HKV + hkv) * DIM) + quad);
                cp16(Vd + row * RS + quad * 4, (const float4*)(v + (pos * HKV + hkv) * DIM) + quad);
            }
            CP_COMMIT();
        }
        const float* Kt = pool3 + (it & 1) * 9728;
        const float* Vt = Kt + 4864;
        const int b = blkList[it];
        const int base = b * LB;

        if (base > s) continue;
        const bool selAct = (selMine >> b) & 1u;
        const bool swaAct = (base + 63) >= winLo;
        if (!(selAct || swaAct)) continue;

        // ---- score pass ----
        u64t s1[8], s2[8];
        #pragma unroll
        for (int hh = 0; hh < 8; ++hh) { s1[hh] = 0ull; s2[hh] = 0ull; }
        {
            const ulonglong2* kA = (const ulonglong2*)Kt + lane * RS2;
            const ulonglong2* kB = kA + 32 * RS2;
            #pragma unroll
            for (int d4 = 0; d4 < 16; ++d4) {
                ulonglong2 a = kA[d4];
                ulonglong2 bb = kB[d4];
                #pragma unroll
                for (int hh = 0; hh < 8; ++hh) {
                    ulonglong2 qv = qq2[hh * 17 + d4];
                    ffma2(s1[hh], qv.x, a.x);
                    ffma2(s1[hh], qv.y, a.y);
                    ffma2(s2[hh], qv.x, bb.x);
                    ffma2(s2[hh], qv.y, bb.y);
                }
            }
        }

        const int jhi  = min(63, s - base);
        const int pos1 = base + lane;
        const bool c1 = (lane <= jhi);
        const bool c2 = (lane + 32 <= jhi);
        const bool w1 = c1 && (pos1 >= winLo);
        const bool w2 = c2 && (pos1 + 32 >= winLo);

        float sc1[8], sc2[8];
        float tS = -1e30f, tW = -1e30f;
        #pragma unroll
        for (int hh = 0; hh < 8; ++hh) {
            float2 f1 = unpack2(s1[hh]);
            float2 f2 = unpack2(s2[hh]);
            sc1[hh] = (f1.x + f1.y) * SCALE;
            sc2[hh] = (f2.x + f2.y) * SCALE;
            if (c1) { tS = fmaxf(tS, sc1[hh]); if (w1) tW = fmaxf(tW, sc1[hh]); }
            if (c2) { tS = fmaxf(tS, sc2[hh]); if (w2) tW = fmaxf(tW, sc2[hh]); }
        }
        #pragma unroll
        for (int off = 16; off; off >>= 1) {
            tS = fmaxf(tS, __shfl_xor_sync(~0u, tS, off));
            tW = fmaxf(tW, __shfl_xor_sync(~0u, tW, off));
        }

        const bool doS = selAct;
        const bool doW = swaAct && (tW > -1e29f);
        float t = -1e30f;
        if (doS) t = tS;
        if (doW) t = fmaxf(t, tW);
        if (t > mU) {
            float f = __expf(mU - t);
            u64t f2p = pack2(f, f);
            #pragma unroll
            for (int i = 0; i < 8; ++i) {
                mul2(accS2[i], accS2[i], f2p);
                mul2(accW2[i], accW2[i], f2p);
                mul2(lsw2[i], lsw2[i], f2p);
            }
            mU = t;
        }

        float e1[8], e2[8];
        #pragma unroll
        for (int hh = 0; hh < 8; ++hh) {
            e1[hh] = __expf(sc1[hh] - mU);
            e2[hh] = __expf(sc2[hh] - mU);
        }
        {
            float4* pw = (float4*)probsW2;
            if (c1) {
                pw[lane * 2]     = make_float4(e1[0], e1[1], e1[2], e1[3]);
                pw[lane * 2 + 1] = make_float4(e1[4], e1[5], e1[6], e1[7]);
            }
            if (c2) {
                pw[(lane + 32) * 2]     = make_float4(e2[0], e2[1], e2[2], e2[3]);
                pw[(lane + 32) * 2 + 1] = make_float4(e2[4], e2[5], e2[6], e2[7]);
            }
        }
        u64t sum2[8];
        #pragma unroll
        for (int hh = 0; hh < 8; ++hh) {
            float sS = (doS && c1 ? e1[hh] : 0.f) + (doS && c2 ? e2[hh] : 0.f);
            float sW = (w1 ? e1[hh] : 0.f) + (w2 ? e2[hh] : 0.f);
            sum2[hh] = pack2(sS, sW);
        }
        #pragma unroll
        for (int off = 16; off; off >>= 1) {
            #pragma unroll
            for (int hh = 0; hh < 8; ++hh) {
                u64t o = __shfl_xor_sync(~0u, sum2[hh], off);
                add2(sum2[hh], sum2[hh], o);
            }
        }
        #pragma unroll
        for (int hh = 0; hh < 8; ++hh) add2(lsw2[hh], lsw2[hh], sum2[hh]);
        __syncwarp();

        // ---- PV pass: lane owns dims (2*lane, 2*lane+1), all 8 heads ----
        const u64t* vB = (const u64t*)Vt + lane;
        const float4* pB = (const float4*)probsW2;
        const int jlo = max(0, winLo - base);

        if (doS && doW) {
            for (int j = 0; j < jlo; ++j) {
                u64t vj = vB[j * RSU];
                float4 pa = pB[j * 2], pb = pB[j * 2 + 1];
                ffma2(accS2[0], pack2(pa.x, pa.x), vj);
                ffma2(accS2[1], pack2(pa.y, pa.y), vj);
                ffma2(accS2[2], pack2(pa.z, pa.z), vj);
                ffma2(accS2[3], pack2(pa.w, pa.w), vj);
                ffma2(accS2[4], pack2(pb.x, pb.x), vj);
                ffma2(accS2[5], pack2(pb.y, pb.y), vj);
                ffma2(accS2[6], pack2(pb.z, pb.z), vj);
                ffma2(accS2[7], pack2(pb.w, pb.w), vj);
            }
            u64t accT2[8];
            #pragma unroll
            for (int i = 0; i < 8; ++i) accT2[i] = 0ull;
            for (int j = jlo; j <= jhi; ++j) {
                u64t vj = vB[j * RSU];
                float4 pa = pB[j * 2], pb = pB[j * 2 + 1];
                ffma2(accT2[0], pack2(pa.x, pa.x), vj);
                ffma2(accT2[1], pack2(pa.y, pa.y), vj);
                ffma2(accT2[2], pack2(pa.z, pa.z), vj);
                ffma2(accT2[3], pack2(pa.w, pa.w), vj);
                ffma2(accT2[4], pack2(pb.x, pb.x), vj);
                ffma2(accT2[5], pack2(pb.y, pb.y), vj);
                ffma2(accT2[6], pack2(pb.z, pb.z), vj);
                ffma2(accT2[7], pack2(pb.w, pb.w), vj);
            }
            #pragma unroll
            for (int i = 0; i < 8; ++i) {
                add2(accS2[i], accS2[i], accT2[i]);
                add2(accW2[i], accW2[i], accT2[i]);
            }
        } else if (doS) {
            for (int j = 0; j <= jhi; ++j) {
                u64t vj = vB[j * RSU];
                float4 pa = pB[j * 2], pb = pB[j * 2 + 1];
                ffma2(accS2[0], pack2(pa.x, pa.x), vj);
                ffma2(accS2[1], pack2(pa.y, pa.y), vj);
                ffma2(accS2[2], pack2(pa.z, pa.z), vj);
                ffma2(accS2[3], pack2(pa.w, pa.w), vj);
                ffma2(accS2[4], pack2(pb.x, pb.x), vj);
                ffma2(accS2[5], pack2(pb.y, pb.y), vj);
                ffma2(accS2[6], pack2(pb.z, pb.z), vj);
                ffma2(accS2[7], pack2(pb.w, pb.w), vj);
            }
        } else if (doW) {
            for (int j = jlo; j <= jhi; ++j) {
                u64t vj = vB[j * RSU];
                float4 pa = pB[j * 2], pb = pB[j * 2 + 1];
                ffma2(accW2[0], pack2(pa.x, pa.x), vj);
                ffma2(accW2[1], pack2(pa.y, pa.y), vj);
                ffma2(accW2[2], pack2(pa.z, pa.z), vj);
                ffma2(accW2[3], pack2(pa.w, pa.w), vj);
                ffma2(accW2[4], pack2(pb.x, pb.x), vj);
                ffma2(accW2[5], pack2(pb.y, pb.y), vj);
                ffma2(accW2[6], pack2(pb.z, pb.z), vj);
                ffma2(accW2[7], pack2(pb.w, pb.w), vj);
            }
        }
    }

    // ---- combine per head, RMW of phase-1 result ----
    #pragma unroll
    for (int hh = 0; hh < 8; ++hh) {
        float g0 = __shfl_sync(~0u, gate0, hh * 4);
        float g1 = __shfl_sync(~0u, gate1, hh * 4);
        float2 lw = unpack2(lsw2[hh]);
        float invS = g0 / fmaxf(lw.x, 1e-20f);
        float invW = g1 / fmaxf(lw.y, 1e-20f);
        float2 aS = unpack2(accS2[hh]);
        float2 aW = unpack2(accW2[hh]);
        float2* op = (float2*)(out + (s * HQ + hkv * GQA + hh) * DIM + 2 * lane);
        float2 cur = *op;
        cur.x += invS * aS.x + invW * aW.x;
        cur.y += invS * aS.y + invW * aW.y;
        *op = cur;
    }
}

// ---------------------------------------------------------------------------
extern "C" void kernel_launch(void* const* d_in, const int* in_sizes, int n_in,
                              void* d_out, int out_size)
{
    const float* q  = (const float*)d_in[0];
    const float* k  = (const float*)d_in[1];
    const float* v  = (const float*)d_in[2];
    const float* wk = (const float*)d_in[3];
    const float* wv = (const float*)d_in[4];
    const float* wg = (const float*)d_in[5];
    float* out = (float*)d_out;

    compress_kernel<<<256, NT>>>(k, v, wk, wv);

    const size_t smem_bytes = 27904 * sizeof(float);   // 111616 B
    cudaFuncSetAttribute(nsa_main,
                         cudaFuncAttributeMaxDynamicSharedMemorySize, (int)smem_bytes);
    nsa_main<<<(S_LEN / QT) * HKV, NT, smem_bytes>>>(q, k, v, wg, out);
}